// round 14
// baseline (speedup 1.0000x reference)
#include <cuda_runtime.h>
#include <cuda_bf16.h>
#include <cuda_fp16.h>
#include <math.h>
#include <stdint.h>

#define NN 20000
#define CC 32
#define TT 8
#define HH 4
#define FF 256
#define HF 1024
#define EE 320000
#define CT 256
#define BEPS 1e-5f
#define SLOPE 0.2f

#define MPAD 20096
#define KP 512
#define SAPITCH 72
#define MM2 160000
#define KA1 192
#define KA2 768

typedef unsigned long long ull;

// ---------------- scratch ----------------
__device__ float d_res[NN*CT];
__device__ float d_xn[NN*CT];
__device__ __half d_hh[(size_t)NN*HF];
__device__ float d_rst[NN*HF];
__device__ float d_el[NN*HH];
__device__ float d_er[NN*HH];
__device__ int   d_counts[NN];
__device__ int   d_rowstart[NN+1];
__device__ int   d_wptr[NN];
__device__ int   d_colsrc[EE];
__device__ float d_bn0sum[64];
__device__ float d_bn1sum[2048];
__device__ float d_bn2sum[64];
__device__ float d_ssc0[32];
__device__ float d_ssh0[32];
__device__ float d_bvec[1024];
__device__ float d_ssc[1024];
__device__ float d_ssh[1024];
__device__ __nv_bfloat16 d_apk[(size_t)MPAD*KP];
__device__ __nv_bfloat16 d_bpk[(size_t)HF*KP];
__device__ __nv_bfloat16 d_ai1[(size_t)MM2*KA1];
__device__ __nv_bfloat16 d_ai2[(size_t)MM2*KA2];
__device__ __nv_bfloat16 d_bp1[128*KA1];
__device__ __nv_bfloat16 d_bp2[128*KA2];

// ---------------- helpers ----------------
__device__ __forceinline__ void cpasync16(uint32_t saddr, const void* g) {
    asm volatile("cp.async.cg.shared.global [%0], [%1], 16;" :: "r"(saddr), "l"(g));
}
__device__ __forceinline__ void hilo(float v, __nv_bfloat16& h, __nv_bfloat16& l) {
    h = __float2bfloat16(v);
    l = __float2bfloat16(v - __bfloat162float(h));
}
__device__ __forceinline__ void h2f(unsigned u, float& a, float& b) {
    __half2 h = *(__half2*)&u;
    float2 f = __half22float2(h);
    a = f.x; b = f.y;
}
__device__ __forceinline__ void mma16816(float* c, const unsigned* a, const unsigned* b) {
    asm volatile(
        "mma.sync.aligned.m16n8k16.row.col.f32.bf16.bf16.f32 "
        "{%0,%1,%2,%3}, {%4,%5,%6,%7}, {%8,%9}, {%0,%1,%2,%3};\n"
        : "+f"(c[0]), "+f"(c[1]), "+f"(c[2]), "+f"(c[3])
        : "r"(a[0]), "r"(a[1]), "r"(a[2]), "r"(a[3]), "r"(b[0]), "r"(b[1]));
}

// ---------------- front im2col pack: X -> d_ai1 ----------------
__global__ __launch_bounds__(256) void k_front_pack(const float* __restrict__ X) {
    int idx = blockIdx.x * 256 + threadIdx.x;
    int m = idx >> 5, ci = idx & 31;
    int n = m >> 3, t = m & 7;
    int base = n*256 + ci*8 + t;
    float x0 = X[base];
    float xm = (t > 0) ? X[base-1] : 0.f;
    float xp = (t < 7) ? X[base+1] : 0.f;
    __nv_bfloat16 h0,l0,h1,l1,h2,l2;
    hilo(xm,h0,l0); hilo(x0,h1,l1); hilo(xp,h2,l2);
    size_t ab = (size_t)m*KA1 + ci*3;
    d_ai1[ab+0]=h0; d_ai1[ab+1]=h1; d_ai1[ab+2]=h2;
    d_ai1[ab+96+0]=l0; d_ai1[ab+96+1]=l1; d_ai1[ab+96+2]=l2;
}

// ---------------- front B pack ----------------
__global__ void k_packB1(const float* __restrict__ w1, const float* __restrict__ w2,
                         const float* __restrict__ w3, const float* __restrict__ rp) {
    int i = blockIdx.x * 256 + threadIdx.x;
    if (i < 3072) {
        int co = i / 96, r = i % 96;
        __nv_bfloat16 h,l;
        hilo(w1[i],h,l); d_bp1[(co)*KA1 + r] = h;      d_bp1[(co)*KA1 + 96 + r] = l;
        hilo(w2[i],h,l); d_bp1[(32+co)*KA1 + r] = h;   d_bp1[(32+co)*KA1 + 96 + r] = l;
        hilo(w3[i],h,l); d_bp1[(64+co)*KA1 + r] = h;   d_bp1[(64+co)*KA1 + 96 + r] = l;
    } else if (i < 4096) {
        int j = i - 3072, co = j >> 5, ci = j & 31;
        __nv_bfloat16 h,l; hilo(rp[j],h,l);
        d_bp1[(96+co)*KA1 + ci*3 + 1] = h;
        d_bp1[(96+co)*KA1 + 96 + ci*3 + 1] = l;
    }
}

// ---------------- front GEMM + gating epilogue (writes apk directly) --------
__global__ __launch_bounds__(256) void k_gemm_front(
    const float* __restrict__ b1, const float* __restrict__ b2,
    const float* __restrict__ b3, const float* __restrict__ rpb)
{
    extern __shared__ __align__(16) char gsm[];
    __nv_bfloat16* As = (__nv_bfloat16*)gsm;
    __nv_bfloat16* Bs = As + 2*128*40;
    int tid = threadIdx.x;
    int m0 = blockIdx.x * 128;
    int w = tid >> 5, lane = tid & 31;
    int wm = (w >> 2) * 64, wn = (w & 3) * 32;
    int g = lane >> 2, t = lane & 3;
    uint32_t sA = (uint32_t)__cvta_generic_to_shared(As);
    uint32_t sB = (uint32_t)__cvta_generic_to_shared(Bs);

    const int kaofs[9] = {0,32,64, 96,128,160, 0,32,64};
    const int kbofs[9] = {0,32,64, 0,32,64, 96,128,160};

    float acc[4][4][4];
    #pragma unroll
    for (int i = 0; i < 4; i++)
        #pragma unroll
        for (int j = 0; j < 4; j++)
            #pragma unroll
            for (int q = 0; q < 4; q++) acc[i][j][q] = 0.f;

    #pragma unroll
    for (int r = 0; r < 2; r++) {
        int l = tid + r*256, row = l >> 2, col = (l & 3) * 8;
        cpasync16(sA + (row*40 + col)*2, &d_ai1[(size_t)(m0+row)*KA1 + col]);
        cpasync16(sB + (row*40 + col)*2, &d_bp1[row*KA1 + col]);
    }
    asm volatile("cp.async.commit_group;");

    for (int it = 0; it < 9; it++) {
        if (it < 8) {
            int ka = kaofs[it+1], kb = kbofs[it+1], buf = (it+1) & 1;
            #pragma unroll
            for (int r = 0; r < 2; r++) {
                int l = tid + r*256, row = l >> 2, col = (l & 3) * 8;
                cpasync16(sA + (buf*5120 + row*40 + col)*2, &d_ai1[(size_t)(m0+row)*KA1 + ka + col]);
                cpasync16(sB + (buf*5120 + row*40 + col)*2, &d_bp1[row*KA1 + kb + col]);
            }
            asm volatile("cp.async.commit_group;");
            asm volatile("cp.async.wait_group 1;");
        } else {
            asm volatile("cp.async.wait_group 0;");
        }
        __syncthreads();
        const __nv_bfloat16* Ab = As + (it & 1)*5120;
        const __nv_bfloat16* Bb = Bs + (it & 1)*5120;
        #pragma unroll
        for (int kk = 0; kk < 2; kk++) {
            int kbx = kk * 16;
            unsigned afr[4][4];
            #pragma unroll
            for (int mi = 0; mi < 4; mi++) {
                int r0 = wm + mi*16 + g;
                afr[mi][0] = *(const unsigned*)&Ab[r0    *40 + kbx + 2*t];
                afr[mi][1] = *(const unsigned*)&Ab[(r0+8)*40 + kbx + 2*t];
                afr[mi][2] = *(const unsigned*)&Ab[r0    *40 + kbx + 2*t + 8];
                afr[mi][3] = *(const unsigned*)&Ab[(r0+8)*40 + kbx + 2*t + 8];
            }
            unsigned bfr[4][2];
            #pragma unroll
            for (int nj = 0; nj < 4; nj++) {
                int br = wn + nj*8 + g;
                bfr[nj][0] = *(const unsigned*)&Bb[br*40 + kbx + 2*t];
                bfr[nj][1] = *(const unsigned*)&Bb[br*40 + kbx + 2*t + 8];
            }
            #pragma unroll
            for (int mi = 0; mi < 4; mi++)
                #pragma unroll
                for (int nj = 0; nj < 4; nj++)
                    mma16816(acc[mi][nj], afr[mi], bfr[nj]);
        }
        __syncthreads();
    }

    float* sm = (float*)gsm;
    float* sstats = sm + 128*132;
    #pragma unroll
    for (int mi = 0; mi < 4; mi++) {
        int r0 = wm + mi*16 + g;
        #pragma unroll
        for (int nj = 0; nj < 4; nj++) {
            int col = wn + nj*8 + 2*t;
            *(float2*)&sm[r0*132 + col]     = make_float2(acc[mi][nj][0], acc[mi][nj][1]);
            *(float2*)&sm[(r0+8)*132 + col] = make_float2(acc[mi][nj][2], acc[mi][nj][3]);
        }
    }
    if (tid < 64) sstats[tid] = 0.f;
    __syncthreads();

    int nb = m0 >> 3;
    float B1 = b1[lane], B2 = b2[lane], B3 = b3[lane], BR = rpb[lane];
    float s = 0.f, q = 0.f;
    #pragma unroll
    for (int rep = 0; rep < 2; rep++) {
        int nl = rep*8 + w;
        int n = nb + nl;
        __nv_bfloat16 hbuf[8], lbuf[8];
        float r8[8];
        #pragma unroll
        for (int tt = 0; tt < 8; tt++) {
            const float* rw = &sm[(nl*8 + tt)*132];
            float a1 = rw[lane] + B1, a2 = rw[lane+32] + B2;
            float a3 = rw[lane+64] + B3, rr = rw[lane+96] + BR;
            float gg = a1*(1.f/(1.f+expf(-a2))) + a3;
            gg = fmaxf(gg, 0.f);
            hilo(gg, hbuf[tt], lbuf[tt]);
            r8[tt] = rr;
            s += gg; q += gg*gg;
        }
        size_t ab = (size_t)n*KP + lane*8;
        *(uint4*)&d_apk[ab]       = *(uint4*)hbuf;
        *(uint4*)&d_apk[ab + 256] = *(uint4*)lbuf;
        *(float4*)&d_res[n*256 + lane*8]     = make_float4(r8[0],r8[1],r8[2],r8[3]);
        *(float4*)&d_res[n*256 + lane*8 + 4] = make_float4(r8[4],r8[5],r8[6],r8[7]);
    }
    atomicAdd(&sstats[lane], s);
    atomicAdd(&sstats[32+lane], q);
    __syncthreads();
    if (tid < 32) {
        atomicAdd(&d_bn0sum[tid],    sstats[tid]);
        atomicAdd(&d_bn0sum[32+tid], sstats[32+tid]);
    }
}

// ---------------- bn0 finalize ----------------
__global__ void k_bnfin0(const float* __restrict__ bn0g, const float* __restrict__ bn0b) {
    int t = threadIdx.x;
    if (t < 32) {
        float inv = 1.f/(float)(NN*TT);
        float mean = d_bn0sum[t]*inv;
        float var  = d_bn0sum[32+t]*inv - mean*mean;
        float a = bn0g[t]*rsqrtf(var + BEPS);
        d_ssc0[t] = a; d_ssh0[t] = bn0b[t] - mean*a;
    }
}

// ---------------- GAT B pack (bn0 scale folded) ----------------
__global__ void k_packB(const float* __restrict__ W) {
    int i = blockIdx.x * blockDim.x + threadIdx.x;
    if (i < HF*256) {
        int o = i >> 8, k = i & 255;
        __nv_bfloat16 bh, bl; hilo(W[i] * __ldg(&d_ssc0[k >> 3]), bh, bl);
        size_t base = (size_t)o * KP;
        d_bpk[base + k]       = bh;
        d_bpk[base + 256 + k] = bl;
    }
}

// ---------------- bvec: bn0 shift folded through W ----------------
__global__ void k_bvec(const float* __restrict__ W) {
    int o = blockIdx.x * 8 + (threadIdx.x >> 5);
    int lane = threadIdx.x & 31;
    float s = 0.f;
    for (int k = lane; k < 256; k += 32)
        s += __ldg(&d_ssh0[k >> 3]) * W[o*256 + k];
    #pragma unroll
    for (int off = 16; off; off >>= 1) s += __shfl_xor_sync(0xffffffffu, s, off);
    if (lane == 0) d_bvec[o] = s;
}

// ---------------- GAT GEMM + bvec + fused el/er, fp16 h out ----------------
__global__ __launch_bounds__(256) void k_gemm_tc(const float* __restrict__ attn_l,
                                                 const float* __restrict__ attn_r) {
    extern __shared__ __align__(16) char gsm[];
    __nv_bfloat16* As = (__nv_bfloat16*)gsm;
    __nv_bfloat16* Bs = As + 2*128*SAPITCH;

    int tid = threadIdx.x;
    int m0 = blockIdx.x * 128, n0 = blockIdx.y * 128;
    int w = tid >> 5, lane = tid & 31;
    int wm = (w >> 2) * 64, wn = (w & 3) * 32;
    int g = lane >> 2, t = lane & 3;

    uint32_t sA = (uint32_t)__cvta_generic_to_shared(As);
    uint32_t sB = (uint32_t)__cvta_generic_to_shared(Bs);

    float acc[4][4][4];
    #pragma unroll
    for (int i = 0; i < 4; i++)
        #pragma unroll
        for (int j = 0; j < 4; j++)
            #pragma unroll
            for (int q = 0; q < 4; q++) acc[i][j][q] = 0.f;

    int row4 = tid >> 3, ci4 = tid & 7;

    #pragma unroll
    for (int r = 0; r < 4; r++) {
        int row = row4 + r*32;
        cpasync16(sA + (row*SAPITCH + ci4*8)*2, &d_apk[(size_t)(m0 + row)*KP + ci4*8]);
        cpasync16(sB + (row*SAPITCH + ci4*8)*2, &d_bpk[(size_t)(n0 + row)*KP + ci4*8]);
    }
    asm volatile("cp.async.commit_group;");

    for (int it = 0; it < 12; it++) {
        if (it < 11) {
            int k0 = (it + 1) * 64;
            int ka = (k0 < 512) ? k0 : k0 - 512;
            int kb = (k0 < 256) ? k0 : k0 - 256;
            int buf = (it + 1) & 1;
            #pragma unroll
            for (int r = 0; r < 4; r++) {
                int row = row4 + r*32;
                cpasync16(sA + (buf*128*SAPITCH + row*SAPITCH + ci4*8)*2,
                          &d_apk[(size_t)(m0 + row)*KP + ka + ci4*8]);
                cpasync16(sB + (buf*128*SAPITCH + row*SAPITCH + ci4*8)*2,
                          &d_bpk[(size_t)(n0 + row)*KP + kb + ci4*8]);
            }
            asm volatile("cp.async.commit_group;");
            asm volatile("cp.async.wait_group 1;");
        } else {
            asm volatile("cp.async.wait_group 0;");
        }
        __syncthreads();

        const __nv_bfloat16* Ab = As + (it & 1)*128*SAPITCH;
        const __nv_bfloat16* Bb = Bs + (it & 1)*128*SAPITCH;
        #pragma unroll
        for (int kk = 0; kk < 4; kk++) {
            int kbx = kk * 16;
            unsigned afr[4][4];
            #pragma unroll
            for (int mi = 0; mi < 4; mi++) {
                int r0 = wm + mi*16 + g;
                afr[mi][0] = *(const unsigned*)&Ab[r0      *SAPITCH + kbx + 2*t];
                afr[mi][1] = *(const unsigned*)&Ab[(r0 + 8)*SAPITCH + kbx + 2*t];
                afr[mi][2] = *(const unsigned*)&Ab[r0      *SAPITCH + kbx + 2*t + 8];
                afr[mi][3] = *(const unsigned*)&Ab[(r0 + 8)*SAPITCH + kbx + 2*t + 8];
            }
            unsigned bfr[4][2];
            #pragma unroll
            for (int nj = 0; nj < 4; nj++) {
                int br = wn + nj*8 + g;
                bfr[nj][0] = *(const unsigned*)&Bb[br*SAPITCH + kbx + 2*t];
                bfr[nj][1] = *(const unsigned*)&Bb[br*SAPITCH + kbx + 2*t + 8];
            }
            #pragma unroll
            for (int mi = 0; mi < 4; mi++)
                #pragma unroll
                for (int nj = 0; nj < 4; nj++)
                    mma16816(acc[mi][nj], afr[mi], bfr[nj]);
        }
        __syncthreads();
    }

    // add bvec (bn0 shift folded through W)
    #pragma unroll
    for (int nj = 0; nj < 4; nj++) {
        int col = n0 + wn + nj*8 + 2*t;
        float bv0 = __ldg(&d_bvec[col]), bv1 = __ldg(&d_bvec[col+1]);
        #pragma unroll
        for (int mi = 0; mi < 4; mi++) {
            acc[mi][nj][0] += bv0; acc[mi][nj][1] += bv1;
            acc[mi][nj][2] += bv0; acc[mi][nj][3] += bv1;
        }
    }

    float pel[4][2], per_[4][2];
    #pragma unroll
    for (int mi = 0; mi < 4; mi++) { pel[mi][0]=pel[mi][1]=per_[mi][0]=per_[mi][1]=0.f; }
    #pragma unroll
    for (int mi = 0; mi < 4; mi++)
        #pragma unroll
        for (int nj = 0; nj < 4; nj++) {
            int col = n0 + wn + nj*8 + 2*t;
            float al0 = __ldg(&attn_l[col]), al1 = __ldg(&attn_l[col+1]);
            float ar0 = __ldg(&attn_r[col]), ar1 = __ldg(&attn_r[col+1]);
            pel[mi][0]  += acc[mi][nj][0]*al0 + acc[mi][nj][1]*al1;
            pel[mi][1]  += acc[mi][nj][2]*al0 + acc[mi][nj][3]*al1;
            per_[mi][0] += acc[mi][nj][0]*ar0 + acc[mi][nj][1]*ar1;
            per_[mi][1] += acc[mi][nj][2]*ar0 + acc[mi][nj][3]*ar1;
        }
    #pragma unroll
    for (int mi = 0; mi < 4; mi++)
        #pragma unroll
        for (int h2 = 0; h2 < 2; h2++) {
            pel[mi][h2]  += __shfl_xor_sync(0xffffffffu, pel[mi][h2], 1);
            pel[mi][h2]  += __shfl_xor_sync(0xffffffffu, pel[mi][h2], 2);
            per_[mi][h2] += __shfl_xor_sync(0xffffffffu, per_[mi][h2], 1);
            per_[mi][h2] += __shfl_xor_sync(0xffffffffu, per_[mi][h2], 2);
        }
    int head = n0 >> 8;
    if (t == 0) {
        #pragma unroll
        for (int mi = 0; mi < 4; mi++) {
            int r0 = m0 + wm + mi*16 + g;
            if (r0 < NN)     { atomicAdd(&d_el[r0*4 + head], pel[mi][0]);
                               atomicAdd(&d_er[r0*4 + head], per_[mi][0]); }
            if (r0 + 8 < NN) { atomicAdd(&d_el[(r0+8)*4 + head], pel[mi][1]);
                               atomicAdd(&d_er[(r0+8)*4 + head], per_[mi][1]); }
        }
    }

    #pragma unroll
    for (int mi = 0; mi < 4; mi++) {
        int r0 = m0 + wm + mi*16 + g;
        #pragma unroll
        for (int nj = 0; nj < 4; nj++) {
            int col = n0 + wn + nj*8 + 2*t;
            if (r0 < NN)
                *(__half2*)&d_hh[(size_t)r0*HF + col] =
                    __float22half2_rn(make_float2(acc[mi][nj][0], acc[mi][nj][1]));
            if (r0 + 8 < NN)
                *(__half2*)&d_hh[(size_t)(r0+8)*HF + col] =
                    __float22half2_rn(make_float2(acc[mi][nj][2], acc[mi][nj][3]));
        }
    }
}

// ---------------- CSR build ----------------
__global__ void k_count(const int* __restrict__ dst) {
    int e = blockIdx.x * blockDim.x + threadIdx.x;
    if (e < EE) atomicAdd(&d_counts[dst[e]], 1);
}

__global__ __launch_bounds__(1024) void k_scan() {
    __shared__ int part[1024];
    int tid = threadIdx.x;
    int beg = tid * 20, end = min(beg + 20, NN);
    int s = 0;
    for (int i = beg; i < end; i++) s += d_counts[i];
    part[tid] = s;
    __syncthreads();
    for (int off = 1; off < 1024; off <<= 1) {
        int v = 0;
        if (tid >= off) v = part[tid - off];
        __syncthreads();
        if (tid >= off) part[tid] += v;
        __syncthreads();
    }
    int run = (tid == 0) ? 0 : part[tid - 1];
    for (int i = beg; i < end; i++) {
        d_rowstart[i] = run; d_wptr[i] = run;
        run += d_counts[i];
    }
    if (tid == 1023) d_rowstart[NN] = run;
}

__global__ void k_fill(const int* __restrict__ src, const int* __restrict__ dst) {
    int e = blockIdx.x * blockDim.x + threadIdx.x;
    if (e < EE) {
        int p = atomicAdd(&d_wptr[dst[e]], 1);
        d_colsrc[p] = src[e];
    }
}

// ---------------- GAT aggregation (fp16 gather) ----------------
__device__ __forceinline__ float lrelu(float x) { return x > 0.f ? x : SLOPE * x; }

__global__ __launch_bounds__(256) void k_agg(const float* __restrict__ bias) {
    int n = (blockIdx.x * blockDim.x + threadIdx.x) >> 5;
    int lane = threadIdx.x & 31;
    if (n >= NN) return;
    int beg = d_rowstart[n], end = d_rowstart[n+1];
    float er0 = d_er[n*4+0], er1 = d_er[n*4+1], er2 = d_er[n*4+2], er3 = d_er[n*4+3];

    float e0[4], e1[4], e2[4], e3[4];
    #pragma unroll
    for (int s = 0; s < 4; s++) {
        int j = beg + s*32 + lane;
        if (j < end) {
            int sc = d_colsrc[j];
            e0[s] = lrelu(d_el[sc*4+0] + er0);
            e1[s] = lrelu(d_el[sc*4+1] + er1);
            e2[s] = lrelu(d_el[sc*4+2] + er2);
            e3[s] = lrelu(d_el[sc*4+3] + er3);
        } else { e0[s] = e1[s] = e2[s] = e3[s] = -1e30f; }
    }
    float m0 = -1e30f, m1 = -1e30f, m2 = -1e30f, m3 = -1e30f;
    #pragma unroll
    for (int s = 0; s < 4; s++) {
        m0 = fmaxf(m0, e0[s]); m1 = fmaxf(m1, e1[s]);
        m2 = fmaxf(m2, e2[s]); m3 = fmaxf(m3, e3[s]);
    }
    #pragma unroll
    for (int off = 16; off; off >>= 1) {
        m0 = fmaxf(m0, __shfl_xor_sync(0xffffffffu, m0, off));
        m1 = fmaxf(m1, __shfl_xor_sync(0xffffffffu, m1, off));
        m2 = fmaxf(m2, __shfl_xor_sync(0xffffffffu, m2, off));
        m3 = fmaxf(m3, __shfl_xor_sync(0xffffffffu, m3, off));
    }
    float s0 = 0.f, s1 = 0.f, s2 = 0.f, s3 = 0.f;
    #pragma unroll
    for (int s = 0; s < 4; s++) {
        e0[s] = expf(e0[s] - m0); s0 += e0[s];
        e1[s] = expf(e1[s] - m1); s1 += e1[s];
        e2[s] = expf(e2[s] - m2); s2 += e2[s];
        e3[s] = expf(e3[s] - m3); s3 += e3[s];
    }
    #pragma unroll
    for (int off = 16; off; off >>= 1) {
        s0 += __shfl_xor_sync(0xffffffffu, s0, off);
        s1 += __shfl_xor_sync(0xffffffffu, s1, off);
        s2 += __shfl_xor_sync(0xffffffffu, s2, off);
        s3 += __shfl_xor_sync(0xffffffffu, s3, off);
    }
    float i0 = s0 > 0.f ? 1.f/s0 : 0.f;
    float i1 = s1 > 0.f ? 1.f/s1 : 0.f;
    float i2 = s2 > 0.f ? 1.f/s2 : 0.f;
    float i3 = s3 > 0.f ? 1.f/s3 : 0.f;
    #pragma unroll
    for (int s = 0; s < 4; s++) { e0[s] *= i0; e1[s] *= i1; e2[s] *= i2; e3[s] *= i3; }

    float acc[4][8];
    #pragma unroll
    for (int j = 0; j < 4; j++)
        #pragma unroll
        for (int e = 0; e < 8; e++) acc[j][e] = 0.f;

    #pragma unroll
    for (int s = 0; s < 4; s++) {
        int base = beg + s*32;
        int lim = end - base;
        if (lim <= 0) break;
        if (lim > 32) lim = 32;
        for (int u = 0; u < lim; u++) {
            int sc = d_colsrc[base + u];
            float wj[4];
            wj[0] = __shfl_sync(0xffffffffu, e0[s], u);
            wj[1] = __shfl_sync(0xffffffffu, e1[s], u);
            wj[2] = __shfl_sync(0xffffffffu, e2[s], u);
            wj[3] = __shfl_sync(0xffffffffu, e3[s], u);
            const uint4* hp = (const uint4*)&d_hh[(size_t)sc*HF];
            #pragma unroll
            for (int j = 0; j < 4; j++) {
                uint4 v = hp[j*32 + lane];
                float w = wj[j];
                float a, b;
                h2f(v.x, a, b); acc[j][0] += w*a; acc[j][1] += w*b;
                h2f(v.y, a, b); acc[j][2] += w*a; acc[j][3] += w*b;
                h2f(v.z, a, b); acc[j][4] += w*a; acc[j][5] += w*b;
                h2f(v.w, a, b); acc[j][6] += w*a; acc[j][7] += w*b;
            }
        }
    }
    #pragma unroll
    for (int j = 0; j < 4; j++) {
        int f0 = j*256 + lane*8;
        float4 b0 = __ldg((const float4*)&bias[f0]);
        float4 b1 = __ldg((const float4*)&bias[f0+4]);
        float4 v0 = make_float4(fmaxf(acc[j][0]+b0.x,0.f), fmaxf(acc[j][1]+b0.y,0.f),
                                fmaxf(acc[j][2]+b0.z,0.f), fmaxf(acc[j][3]+b0.w,0.f));
        float4 v1 = make_float4(fmaxf(acc[j][4]+b1.x,0.f), fmaxf(acc[j][5]+b1.y,0.f),
                                fmaxf(acc[j][6]+b1.z,0.f), fmaxf(acc[j][7]+b1.w,0.f));
        *(float4*)&d_rst[(size_t)n*HF + f0]     = v0;
        *(float4*)&d_rst[(size_t)n*HF + f0 + 4] = v1;
    }
}

// ---------------- bn1 stats ----------------
__global__ __launch_bounds__(256) void k_bn1stats() {
    int f = blockIdx.x * 256 + threadIdx.x;
    int n0 = blockIdx.y * 500;
    float s = 0.f, q = 0.f;
    for (int n = n0; n < n0 + 500; n++) {
        float v = d_rst[(size_t)n*HF + f];
        s += v; q += v*v;
    }
    atomicAdd(&d_bn1sum[f], s);
    atomicAdd(&d_bn1sum[1024 + f], q);
}

__global__ void k_bnfin1(const float* __restrict__ bn1g, const float* __restrict__ bn1b) {
    int f = blockIdx.x * 256 + threadIdx.x;
    if (f < 1024) {
        float invN = 1.f/(float)NN;
        float mean = d_bn1sum[f]*invN;
        float var  = d_bn1sum[1024+f]*invN - mean*mean;
        float a = bn1g[f]*rsqrtf(var + BEPS);
        d_ssc[f] = a; d_ssh[f] = bn1b[f] - mean*a;
    }
}

// ---------------- gated2 im2col pack (bn1 apply fused) ----------------
__global__ __launch_bounds__(256) void k_g2_pack() {
    int idx = blockIdx.x * 256 + threadIdx.x;
    int m = idx >> 7, ci = idx & 127;
    int n = m >> 3, t = m & 7;
    int f = ci*8 + t;
    const float* rr = &d_rst[(size_t)n*HF];
    float x0 = rr[f]*__ldg(&d_ssc[f]) + __ldg(&d_ssh[f]);
    float xm = (t > 0) ? rr[f-1]*__ldg(&d_ssc[f-1]) + __ldg(&d_ssh[f-1]) : 0.f;
    float xp = (t < 7) ? rr[f+1]*__ldg(&d_ssc[f+1]) + __ldg(&d_ssh[f+1]) : 0.f;
    __nv_bfloat16 h0,l0,h1,l1,h2,l2;
    hilo(xm,h0,l0); hilo(x0,h1,l1); hilo(xp,h2,l2);
    size_t ab = (size_t)m*KA2 + ci*3;
    d_ai2[ab+0]=h0; d_ai2[ab+1]=h1; d_ai2[ab+2]=h2;
    d_ai2[ab+384+0]=l0; d_ai2[ab+384+1]=l1; d_ai2[ab+384+2]=l2;
}

// ---------------- gated2 B pack ----------------
__global__ void k_packB2(const float* __restrict__ w1, const float* __restrict__ w2,
                         const float* __restrict__ w3) {
    int i = blockIdx.x * 256 + threadIdx.x;
    if (i < 12288) {
        int co = i / 384, r = i % 384;
        __nv_bfloat16 h,l;
        hilo(w1[i],h,l); d_bp2[(co)*KA2 + r] = h;    d_bp2[(co)*KA2 + 384 + r] = l;
        hilo(w2[i],h,l); d_bp2[(32+co)*KA2 + r] = h; d_bp2[(32+co)*KA2 + 384 + r] = l;
        hilo(w3[i],h,l); d_bp2[(64+co)*KA2 + r] = h; d_bp2[(64+co)*KA2 + 384 + r] = l;
    }
}

// ---------------- gated2 GEMM (N=96) + gating epilogue ----------------
__global__ __launch_bounds__(256) void k_gemm_g2(
    const float* __restrict__ b1, const float* __restrict__ b2,
    const float* __restrict__ b3)
{
    extern __shared__ __align__(16) char gsm[];
    __nv_bfloat16* As = (__nv_bfloat16*)gsm;                 // [2][128*72]
    __nv_bfloat16* Bs = As + 2*128*SAPITCH;                  // [2][96*72]
    int tid = threadIdx.x;
    int m0 = blockIdx.x * 128;
    int w = tid >> 5, lane = tid & 31;
    int wm = (w >> 2) * 64, wn = (w & 3) * 24;
    int g = lane >> 2, t = lane & 3;
    uint32_t sA = (uint32_t)__cvta_generic_to_shared(As);
    uint32_t sB = (uint32_t)__cvta_generic_to_shared(Bs);

    float acc[4][3][4];
    #pragma unroll
    for (int i = 0; i < 4; i++)
        #pragma unroll
        for (int j = 0; j < 3; j++)
            #pragma unroll
            for (int q = 0; q < 4; q++) acc[i][j][q] = 0.f;

    int row4 = tid >> 3, ci4 = tid & 7;

    #pragma unroll
    for (int r = 0; r < 4; r++) {
        int row = row4 + r*32;
        cpasync16(sA + (row*SAPITCH + ci4*8)*2, &d_ai2[(size_t)(m0 + row)*KA2 + ci4*8]);
        if (r < 3)
            cpasync16(sB + (row*SAPITCH + ci4*8)*2, &d_bp2[row*KA2 + ci4*8]);
    }
    asm volatile("cp.async.commit_group;");

    for (int it = 0; it < 18; it++) {
        if (it < 17) {
            int i1 = it + 1;
            int ka = (i1 < 6) ? i1*64 : (i1 < 12) ? 384 + (i1-6)*64 : (i1-12)*64;
            int kb = (i1 < 6) ? i1*64 : (i1 < 12) ? (i1-6)*64 : 384 + (i1-12)*64;
            int buf = i1 & 1;
            #pragma unroll
            for (int r = 0; r < 4; r++) {
                int row = row4 + r*32;
                cpasync16(sA + (buf*128*SAPITCH + row*SAPITCH + ci4*8)*2,
                          &d_ai2[(size_t)(m0 + row)*KA2 + ka + ci4*8]);
                if (r < 3)
                    cpasync16(sB + (buf*96*SAPITCH + row*SAPITCH + ci4*8)*2,
                              &d_bp2[row*KA2 + kb + ci4*8]);
            }
            asm volatile("cp.async.commit_group;");
            asm volatile("cp.async.wait_group 1;");
        } else {
            asm volatile("cp.async.wait_group 0;");
        }
        __syncthreads();
        const __nv_bfloat16* Ab = As + (it & 1)*128*SAPITCH;
        const __nv_bfloat16* Bb = Bs + (it & 1)*96*SAPITCH;
        #pragma unroll
        for (int kk = 0; kk < 4; kk++) {
            int kbx = kk * 16;
            unsigned afr[4][4];
            #pragma unroll
            for (int mi = 0; mi < 4; mi++) {
                int r0 = wm + mi*16 + g;
                afr[mi][0] = *(const unsigned*)&Ab[r0      *SAPITCH + kbx + 2*t];
                afr[mi][1] = *(const unsigned*)&Ab[(r0 + 8)*SAPITCH + kbx + 2*t];
                afr[mi][2] = *(const unsigned*)&Ab[r0      *SAPITCH + kbx + 2*t + 8];
                afr[mi][3] = *(const unsigned*)&Ab[(r0 + 8)*SAPITCH + kbx + 2*t + 8];
            }
            unsigned bfr[3][2];
            #pragma unroll
            for (int nj = 0; nj < 3; nj++) {
                int br = wn + nj*8 + g;
                bfr[nj][0] = *(const unsigned*)&Bb[br*SAPITCH + kbx + 2*t];
                bfr[nj][1] = *(const unsigned*)&Bb[br*SAPITCH + kbx + 2*t + 8];
            }
            #pragma unroll
            for (int mi = 0; mi < 4; mi++)
                #pragma unroll
                for (int nj = 0; nj < 3; nj++)
                    mma16816(acc[mi][nj], afr[mi], bfr[nj]);
        }
        __syncthreads();
    }

    float* sm = (float*)gsm;
    float* sstats = sm + 128*132;
    #pragma unroll
    for (int mi = 0; mi < 4; mi++) {
        int r0 = wm + mi*16 + g;
        #pragma unroll
        for (int nj = 0; nj < 3; nj++) {
            int col = wn + nj*8 + 2*t;
            *(float2*)&sm[r0*132 + col]     = make_float2(acc[mi][nj][0], acc[mi][nj][1]);
            *(float2*)&sm[(r0+8)*132 + col] = make_float2(acc[mi][nj][2], acc[mi][nj][3]);
        }
    }
    if (tid < 64) sstats[tid] = 0.f;
    __syncthreads();

    int nb = m0 >> 3;
    float B1 = b1[lane], B2 = b2[lane], B3 = b3[lane];
    float s = 0.f, q = 0.f;
    #pragma unroll
    for (int rep = 0; rep < 2; rep++) {
        int nl = rep*8 + w;
        int n = nb + nl;
        float g8[8];
        #pragma unroll
        for (int tt = 0; tt < 8; tt++) {
            const float* rw = &sm[(nl*8 + tt)*132];
            float a1 = rw[lane] + B1, a2 = rw[lane+32] + B2, a3 = rw[lane+64] + B3;
            float gg = a1*(1.f/(1.f+expf(-a2))) + a3;
            gg = fmaxf(gg, 0.f);
            g8[tt] = gg;
            s += gg; q += gg*gg;
        }
        *(float4*)&d_xn[n*256 + lane*8]     = make_float4(g8[0],g8[1],g8[2],g8[3]);
        *(float4*)&d_xn[n*256 + lane*8 + 4] = make_float4(g8[4],g8[5],g8[6],g8[7]);
    }
    atomicAdd(&sstats[lane], s);
    atomicAdd(&sstats[32+lane], q);
    __syncthreads();
    if (tid < 32) {
        atomicAdd(&d_bn2sum[tid],    sstats[tid]);
        atomicAdd(&d_bn2sum[32+tid], sstats[32+tid]);
    }
}

// ---------------- final ----------------
__global__ void k_out(float* __restrict__ out, const float* __restrict__ bn2g,
                      const float* __restrict__ bn2b) {
    __shared__ float ssc[32], ssh[32];
    int tid = threadIdx.x;
    if (tid < 32) {
        float inv = 1.f/(float)(NN*TT);
        float mean = d_bn2sum[tid]*inv;
        float var  = d_bn2sum[32+tid]*inv - mean*mean;
        float a = bn2g[tid]*rsqrtf(var + BEPS);
        ssc[tid] = a; ssh[tid] = bn2b[tid] - mean*a;
    }
    __syncthreads();
    int base = blockIdx.x * 2048;
    for (int o = tid; o < 2048; o += 256) {
        int i = base + o;
        if (i < NN*CT) {
            int c = (i >> 3) & 31;
            float v = d_xn[i]*ssc[c] + ssh[c] + d_res[i];
            out[i] = v > 0.f ? v : 0.f;
        }
    }
}

// ---------------- launch ----------------
extern "C" void kernel_launch(void* const* d_in, const int* in_sizes, int n_in,
                              void* d_out, int out_size) {
    const float* X      = (const float*)d_in[0];
    const int*   src    = (const int*)  d_in[1];
    const int*   dst    = (const int*)  d_in[2];
    const float* rp_w   = (const float*)d_in[3];
    const float* rp_b   = (const float*)d_in[4];
    const float* g1w1   = (const float*)d_in[5];
    const float* g1b1   = (const float*)d_in[6];
    const float* g1w2   = (const float*)d_in[7];
    const float* g1b2   = (const float*)d_in[8];
    const float* g1w3   = (const float*)d_in[9];
    const float* g1b3   = (const float*)d_in[10];
    const float* bn0g   = (const float*)d_in[11];
    const float* bn0b   = (const float*)d_in[12];
    const float* gatw   = (const float*)d_in[13];
    const float* attnl  = (const float*)d_in[14];
    const float* attnr  = (const float*)d_in[15];
    const float* gatb   = (const float*)d_in[16];
    const float* bn1g   = (const float*)d_in[17];
    const float* bn1b   = (const float*)d_in[18];
    const float* g2w1   = (const float*)d_in[19];
    const float* g2b1   = (const float*)d_in[20];
    const float* g2w2   = (const float*)d_in[21];
    const float* g2b2   = (const float*)d_in[22];
    const float* g2w3   = (const float*)d_in[23];
    const float* g2b3   = (const float*)d_in[24];
    const float* bn2g   = (const float*)d_in[25];
    const float* bn2b   = (const float*)d_in[26];
    float* out = (float*)d_out;

    static cudaStream_t s2 = 0;
    static cudaEvent_t evF = 0, evJ = 0;
    static int inited = 0;
    if (!inited) {
        cudaFuncSetAttribute(k_gemm_front, cudaFuncAttributeMaxDynamicSharedMemorySize, 73728);
        cudaFuncSetAttribute(k_gemm_tc,    cudaFuncAttributeMaxDynamicSharedMemorySize, 73728);
        cudaFuncSetAttribute(k_gemm_g2,    cudaFuncAttributeMaxDynamicSharedMemorySize, 73728);
        cudaStreamCreateWithFlags(&s2, cudaStreamNonBlocking);
        cudaEventCreateWithFlags(&evF, cudaEventDisableTiming);
        cudaEventCreateWithFlags(&evJ, cudaEventDisableTiming);
        inited = 1;
    }

    void *p_b0, *p_b1, *p_b2, *p_cnt, *p_el, *p_er;
    cudaGetSymbolAddress(&p_b0, d_bn0sum);
    cudaGetSymbolAddress(&p_b1, d_bn1sum);
    cudaGetSymbolAddress(&p_b2, d_bn2sum);
    cudaGetSymbolAddress(&p_cnt, d_counts);
    cudaGetSymbolAddress(&p_el, d_el);
    cudaGetSymbolAddress(&p_er, d_er);

    cudaMemsetAsync(p_b0, 0, 64*sizeof(float));
    cudaMemsetAsync(p_b1, 0, 2048*sizeof(float));
    cudaMemsetAsync(p_b2, 0, 64*sizeof(float));
    cudaMemsetAsync(p_el, 0, NN*HH*sizeof(float));
    cudaMemsetAsync(p_er, 0, NN*HH*sizeof(float));

    // side stream: gated2 B pack + CSR build, overlapped with front/GAT
    cudaEventRecord(evF, 0);
    cudaStreamWaitEvent(s2, evF, 0);
    k_packB2<<<48, 256, 0, s2>>>(g2w1, g2w2, g2w3);
    cudaMemsetAsync(p_cnt, 0, NN*sizeof(int), s2);
    k_count<<<(EE + 255)/256, 256, 0, s2>>>(dst);
    k_scan<<<1, 1024, 0, s2>>>();
    k_fill<<<(EE + 255)/256, 256, 0, s2>>>(src, dst);
    cudaEventRecord(evJ, s2);

    // front: im2col + GEMM (writes apk) + bn0 finalize
    k_packB1<<<16, 256>>>(g1w1, g1w2, g1w3, rp_w);
    k_front_pack<<<MM2*32/256, 256>>>(X);
    k_gemm_front<<<MM2/128, 256, 73728>>>(g1b1, g1b2, g1b3, rp_b);
    k_bnfin0<<<1, 32>>>(bn0g, bn0b);

    // GAT projection GEMM (bn0 folded into W)
    k_packB<<<(HF*256 + 255)/256, 256>>>(gatw);
    k_bvec<<<128, 256>>>(gatw);
    k_gemm_tc<<<dim3(MPAD/128, HF/128), 256, 73728>>>(attnl, attnr);

    cudaStreamWaitEvent(0, evJ, 0);
    k_agg<<<(NN*32 + 255)/256, 256>>>(gatb);
    k_bn1stats<<<dim3(4, 40), 256>>>();
    k_bnfin1<<<4, 256>>>(bn1g, bn1b);

    // gated2: im2col + GEMM + gating epilogue
    k_g2_pack<<<MM2*128/256, 256>>>();
    k_gemm_g2<<<MM2/128, 256, 73728>>>(g2b1, g2b2, g2b3);

    k_out<<<(NN*CT + 2047)/2048, 256>>>(out, bn2g, bn2b);
}

// round 15
// speedup vs baseline: 1.1686x; 1.1686x over previous
#include <cuda_runtime.h>
#include <cuda_bf16.h>
#include <cuda_fp16.h>
#include <math.h>
#include <stdint.h>

#define NN 20000
#define CC 32
#define TT 8
#define HH 4
#define FF 256
#define HF 1024
#define EE 320000
#define CT 256
#define BEPS 1e-5f
#define SLOPE 0.2f

#define MPAD 20096
#define KP 512
#define SAPITCH 72
#define MM2 160000
#define KA1 192
#define KA2H 384

typedef unsigned long long ull;

// ---------------- scratch ----------------
__device__ float d_res[NN*CT];
__device__ float d_xn[NN*CT];
__device__ __half d_hh[(size_t)NN*HF];
__device__ float d_rst[NN*HF];
__device__ float d_el[NN*HH];
__device__ float d_er[NN*HH];
__device__ int   d_counts[NN];
__device__ int   d_rowstart[NN+1];
__device__ int   d_wptr[NN];
__device__ int   d_colsrc[EE];
__device__ float d_bn0sum[64];
__device__ float d_bn1sum[2048];
__device__ float d_bn2sum[64];
__device__ float d_ssc0[32];
__device__ float d_ssh0[32];
__device__ float d_bvec[1024];
__device__ float d_ssc[1024];
__device__ float d_ssh[1024];
__device__ __nv_bfloat16 d_apk[(size_t)MPAD*KP];
__device__ __nv_bfloat16 d_bpk[(size_t)HF*KP];
__device__ __nv_bfloat16 d_ai1[(size_t)MM2*KA1];
__device__ __half d_ai2h[(size_t)MM2*KA2H];
__device__ __nv_bfloat16 d_bp1[128*KA1];
__device__ __half d_bp2h[96*KA2H];

// ---------------- helpers ----------------
__device__ __forceinline__ void cpasync16(uint32_t saddr, const void* g) {
    asm volatile("cp.async.cg.shared.global [%0], [%1], 16;" :: "r"(saddr), "l"(g));
}
__device__ __forceinline__ void hilo(float v, __nv_bfloat16& h, __nv_bfloat16& l) {
    h = __float2bfloat16(v);
    l = __float2bfloat16(v - __bfloat162float(h));
}
__device__ __forceinline__ void h2f(unsigned u, float& a, float& b) {
    __half2 h = *(__half2*)&u;
    float2 f = __half22float2(h);
    a = f.x; b = f.y;
}
__device__ __forceinline__ void mma16816(float* c, const unsigned* a, const unsigned* b) {
    asm volatile(
        "mma.sync.aligned.m16n8k16.row.col.f32.bf16.bf16.f32 "
        "{%0,%1,%2,%3}, {%4,%5,%6,%7}, {%8,%9}, {%0,%1,%2,%3};\n"
        : "+f"(c[0]), "+f"(c[1]), "+f"(c[2]), "+f"(c[3])
        : "r"(a[0]), "r"(a[1]), "r"(a[2]), "r"(a[3]), "r"(b[0]), "r"(b[1]));
}
__device__ __forceinline__ void mma16816h(float* c, const unsigned* a, const unsigned* b) {
    asm volatile(
        "mma.sync.aligned.m16n8k16.row.col.f32.f16.f16.f32 "
        "{%0,%1,%2,%3}, {%4,%5,%6,%7}, {%8,%9}, {%0,%1,%2,%3};\n"
        : "+f"(c[0]), "+f"(c[1]), "+f"(c[2]), "+f"(c[3])
        : "r"(a[0]), "r"(a[1]), "r"(a[2]), "r"(a[3]), "r"(b[0]), "r"(b[1]));
}

// ---------------- front im2col pack: X -> d_ai1 ----------------
__global__ __launch_bounds__(256) void k_front_pack(const float* __restrict__ X) {
    int idx = blockIdx.x * 256 + threadIdx.x;
    int m = idx >> 5, ci = idx & 31;
    int n = m >> 3, t = m & 7;
    int base = n*256 + ci*8 + t;
    float x0 = X[base];
    float xm = (t > 0) ? X[base-1] : 0.f;
    float xp = (t < 7) ? X[base+1] : 0.f;
    __nv_bfloat16 h0,l0,h1,l1,h2,l2;
    hilo(xm,h0,l0); hilo(x0,h1,l1); hilo(xp,h2,l2);
    size_t ab = (size_t)m*KA1 + ci*3;
    d_ai1[ab+0]=h0; d_ai1[ab+1]=h1; d_ai1[ab+2]=h2;
    d_ai1[ab+96+0]=l0; d_ai1[ab+96+1]=l1; d_ai1[ab+96+2]=l2;
}

// ---------------- front B pack ----------------
__global__ void k_packB1(const float* __restrict__ w1, const float* __restrict__ w2,
                         const float* __restrict__ w3, const float* __restrict__ rp) {
    int i = blockIdx.x * 256 + threadIdx.x;
    if (i < 3072) {
        int co = i / 96, r = i % 96;
        __nv_bfloat16 h,l;
        hilo(w1[i],h,l); d_bp1[(co)*KA1 + r] = h;      d_bp1[(co)*KA1 + 96 + r] = l;
        hilo(w2[i],h,l); d_bp1[(32+co)*KA1 + r] = h;   d_bp1[(32+co)*KA1 + 96 + r] = l;
        hilo(w3[i],h,l); d_bp1[(64+co)*KA1 + r] = h;   d_bp1[(64+co)*KA1 + 96 + r] = l;
    } else if (i < 4096) {
        int j = i - 3072, co = j >> 5, ci = j & 31;
        __nv_bfloat16 h,l; hilo(rp[j],h,l);
        d_bp1[(96+co)*KA1 + ci*3 + 1] = h;
        d_bp1[(96+co)*KA1 + 96 + ci*3 + 1] = l;
    }
}

// ---------------- front GEMM + gating epilogue (writes apk directly) --------
__global__ __launch_bounds__(256) void k_gemm_front(
    const float* __restrict__ b1, const float* __restrict__ b2,
    const float* __restrict__ b3, const float* __restrict__ rpb)
{
    extern __shared__ __align__(16) char gsm[];
    __nv_bfloat16* As = (__nv_bfloat16*)gsm;
    __nv_bfloat16* Bs = As + 2*128*40;
    int tid = threadIdx.x;
    int m0 = blockIdx.x * 128;
    int w = tid >> 5, lane = tid & 31;
    int wm = (w >> 2) * 64, wn = (w & 3) * 32;
    int g = lane >> 2, t = lane & 3;
    uint32_t sA = (uint32_t)__cvta_generic_to_shared(As);
    uint32_t sB = (uint32_t)__cvta_generic_to_shared(Bs);

    const int kaofs[9] = {0,32,64, 96,128,160, 0,32,64};
    const int kbofs[9] = {0,32,64, 0,32,64, 96,128,160};

    float acc[4][4][4];
    #pragma unroll
    for (int i = 0; i < 4; i++)
        #pragma unroll
        for (int j = 0; j < 4; j++)
            #pragma unroll
            for (int q = 0; q < 4; q++) acc[i][j][q] = 0.f;

    #pragma unroll
    for (int r = 0; r < 2; r++) {
        int l = tid + r*256, row = l >> 2, col = (l & 3) * 8;
        cpasync16(sA + (row*40 + col)*2, &d_ai1[(size_t)(m0+row)*KA1 + col]);
        cpasync16(sB + (row*40 + col)*2, &d_bp1[row*KA1 + col]);
    }
    asm volatile("cp.async.commit_group;");

    for (int it = 0; it < 9; it++) {
        if (it < 8) {
            int ka = kaofs[it+1], kb = kbofs[it+1], buf = (it+1) & 1;
            #pragma unroll
            for (int r = 0; r < 2; r++) {
                int l = tid + r*256, row = l >> 2, col = (l & 3) * 8;
                cpasync16(sA + (buf*5120 + row*40 + col)*2, &d_ai1[(size_t)(m0+row)*KA1 + ka + col]);
                cpasync16(sB + (buf*5120 + row*40 + col)*2, &d_bp1[row*KA1 + kb + col]);
            }
            asm volatile("cp.async.commit_group;");
            asm volatile("cp.async.wait_group 1;");
        } else {
            asm volatile("cp.async.wait_group 0;");
        }
        __syncthreads();
        const __nv_bfloat16* Ab = As + (it & 1)*5120;
        const __nv_bfloat16* Bb = Bs + (it & 1)*5120;
        #pragma unroll
        for (int kk = 0; kk < 2; kk++) {
            int kbx = kk * 16;
            unsigned afr[4][4];
            #pragma unroll
            for (int mi = 0; mi < 4; mi++) {
                int r0 = wm + mi*16 + g;
                afr[mi][0] = *(const unsigned*)&Ab[r0    *40 + kbx + 2*t];
                afr[mi][1] = *(const unsigned*)&Ab[(r0+8)*40 + kbx + 2*t];
                afr[mi][2] = *(const unsigned*)&Ab[r0    *40 + kbx + 2*t + 8];
                afr[mi][3] = *(const unsigned*)&Ab[(r0+8)*40 + kbx + 2*t + 8];
            }
            unsigned bfr[4][2];
            #pragma unroll
            for (int nj = 0; nj < 4; nj++) {
                int br = wn + nj*8 + g;
                bfr[nj][0] = *(const unsigned*)&Bb[br*40 + kbx + 2*t];
                bfr[nj][1] = *(const unsigned*)&Bb[br*40 + kbx + 2*t + 8];
            }
            #pragma unroll
            for (int mi = 0; mi < 4; mi++)
                #pragma unroll
                for (int nj = 0; nj < 4; nj++)
                    mma16816(acc[mi][nj], afr[mi], bfr[nj]);
        }
        __syncthreads();
    }

    float* sm = (float*)gsm;
    float* sstats = sm + 128*132;
    #pragma unroll
    for (int mi = 0; mi < 4; mi++) {
        int r0 = wm + mi*16 + g;
        #pragma unroll
        for (int nj = 0; nj < 4; nj++) {
            int col = wn + nj*8 + 2*t;
            *(float2*)&sm[r0*132 + col]     = make_float2(acc[mi][nj][0], acc[mi][nj][1]);
            *(float2*)&sm[(r0+8)*132 + col] = make_float2(acc[mi][nj][2], acc[mi][nj][3]);
        }
    }
    if (tid < 64) sstats[tid] = 0.f;
    __syncthreads();

    int nb = m0 >> 3;
    float B1 = b1[lane], B2 = b2[lane], B3 = b3[lane], BR = rpb[lane];
    float s = 0.f, q = 0.f;
    #pragma unroll
    for (int rep = 0; rep < 2; rep++) {
        int nl = rep*8 + w;
        int n = nb + nl;
        __nv_bfloat16 hbuf[8], lbuf[8];
        float r8[8];
        #pragma unroll
        for (int tt = 0; tt < 8; tt++) {
            const float* rw = &sm[(nl*8 + tt)*132];
            float a1 = rw[lane] + B1, a2 = rw[lane+32] + B2;
            float a3 = rw[lane+64] + B3, rr = rw[lane+96] + BR;
            float gg = a1*(1.f/(1.f+expf(-a2))) + a3;
            gg = fmaxf(gg, 0.f);
            hilo(gg, hbuf[tt], lbuf[tt]);
            r8[tt] = rr;
            s += gg; q += gg*gg;
        }
        size_t ab = (size_t)n*KP + lane*8;
        *(uint4*)&d_apk[ab]       = *(uint4*)hbuf;
        *(uint4*)&d_apk[ab + 256] = *(uint4*)lbuf;
        *(float4*)&d_res[n*256 + lane*8]     = make_float4(r8[0],r8[1],r8[2],r8[3]);
        *(float4*)&d_res[n*256 + lane*8 + 4] = make_float4(r8[4],r8[5],r8[6],r8[7]);
    }
    atomicAdd(&sstats[lane], s);
    atomicAdd(&sstats[32+lane], q);
    __syncthreads();
    if (tid < 32) {
        atomicAdd(&d_bn0sum[tid],    sstats[tid]);
        atomicAdd(&d_bn0sum[32+tid], sstats[32+tid]);
    }
}

// ---------------- bn0 finalize ----------------
__global__ void k_bnfin0(const float* __restrict__ bn0g, const float* __restrict__ bn0b) {
    int t = threadIdx.x;
    if (t < 32) {
        float inv = 1.f/(float)(NN*TT);
        float mean = d_bn0sum[t]*inv;
        float var  = d_bn0sum[32+t]*inv - mean*mean;
        float a = bn0g[t]*rsqrtf(var + BEPS);
        d_ssc0[t] = a; d_ssh0[t] = bn0b[t] - mean*a;
    }
}

// ---------------- GAT B pack (bn0 scale folded) ----------------
__global__ void k_packB(const float* __restrict__ W) {
    int i = blockIdx.x * blockDim.x + threadIdx.x;
    if (i < HF*256) {
        int o = i >> 8, k = i & 255;
        __nv_bfloat16 bh, bl; hilo(W[i] * __ldg(&d_ssc0[k >> 3]), bh, bl);
        size_t base = (size_t)o * KP;
        d_bpk[base + k]       = bh;
        d_bpk[base + 256 + k] = bl;
    }
}

// ---------------- bvec ----------------
__global__ void k_bvec(const float* __restrict__ W) {
    int o = blockIdx.x * 8 + (threadIdx.x >> 5);
    int lane = threadIdx.x & 31;
    float s = 0.f;
    for (int k = lane; k < 256; k += 32)
        s += __ldg(&d_ssh0[k >> 3]) * W[o*256 + k];
    #pragma unroll
    for (int off = 16; off; off >>= 1) s += __shfl_xor_sync(0xffffffffu, s, off);
    if (lane == 0) d_bvec[o] = s;
}

// ---------------- GAT GEMM + bvec + fused el/er, fp16 h out ----------------
__global__ __launch_bounds__(256) void k_gemm_tc(const float* __restrict__ attn_l,
                                                 const float* __restrict__ attn_r) {
    extern __shared__ __align__(16) char gsm[];
    __nv_bfloat16* As = (__nv_bfloat16*)gsm;
    __nv_bfloat16* Bs = As + 2*128*SAPITCH;

    int tid = threadIdx.x;
    int m0 = blockIdx.x * 128, n0 = blockIdx.y * 128;
    int w = tid >> 5, lane = tid & 31;
    int wm = (w >> 2) * 64, wn = (w & 3) * 32;
    int g = lane >> 2, t = lane & 3;

    uint32_t sA = (uint32_t)__cvta_generic_to_shared(As);
    uint32_t sB = (uint32_t)__cvta_generic_to_shared(Bs);

    float acc[4][4][4];
    #pragma unroll
    for (int i = 0; i < 4; i++)
        #pragma unroll
        for (int j = 0; j < 4; j++)
            #pragma unroll
            for (int q = 0; q < 4; q++) acc[i][j][q] = 0.f;

    int row4 = tid >> 3, ci4 = tid & 7;

    #pragma unroll
    for (int r = 0; r < 4; r++) {
        int row = row4 + r*32;
        cpasync16(sA + (row*SAPITCH + ci4*8)*2, &d_apk[(size_t)(m0 + row)*KP + ci4*8]);
        cpasync16(sB + (row*SAPITCH + ci4*8)*2, &d_bpk[(size_t)(n0 + row)*KP + ci4*8]);
    }
    asm volatile("cp.async.commit_group;");

    for (int it = 0; it < 12; it++) {
        if (it < 11) {
            int k0 = (it + 1) * 64;
            int ka = (k0 < 512) ? k0 : k0 - 512;
            int kb = (k0 < 256) ? k0 : k0 - 256;
            int buf = (it + 1) & 1;
            #pragma unroll
            for (int r = 0; r < 4; r++) {
                int row = row4 + r*32;
                cpasync16(sA + (buf*128*SAPITCH + row*SAPITCH + ci4*8)*2,
                          &d_apk[(size_t)(m0 + row)*KP + ka + ci4*8]);
                cpasync16(sB + (buf*128*SAPITCH + row*SAPITCH + ci4*8)*2,
                          &d_bpk[(size_t)(n0 + row)*KP + kb + ci4*8]);
            }
            asm volatile("cp.async.commit_group;");
            asm volatile("cp.async.wait_group 1;");
        } else {
            asm volatile("cp.async.wait_group 0;");
        }
        __syncthreads();

        const __nv_bfloat16* Ab = As + (it & 1)*128*SAPITCH;
        const __nv_bfloat16* Bb = Bs + (it & 1)*128*SAPITCH;
        #pragma unroll
        for (int kk = 0; kk < 4; kk++) {
            int kbx = kk * 16;
            unsigned afr[4][4];
            #pragma unroll
            for (int mi = 0; mi < 4; mi++) {
                int r0 = wm + mi*16 + g;
                afr[mi][0] = *(const unsigned*)&Ab[r0      *SAPITCH + kbx + 2*t];
                afr[mi][1] = *(const unsigned*)&Ab[(r0 + 8)*SAPITCH + kbx + 2*t];
                afr[mi][2] = *(const unsigned*)&Ab[r0      *SAPITCH + kbx + 2*t + 8];
                afr[mi][3] = *(const unsigned*)&Ab[(r0 + 8)*SAPITCH + kbx + 2*t + 8];
            }
            unsigned bfr[4][2];
            #pragma unroll
            for (int nj = 0; nj < 4; nj++) {
                int br = wn + nj*8 + g;
                bfr[nj][0] = *(const unsigned*)&Bb[br*SAPITCH + kbx + 2*t];
                bfr[nj][1] = *(const unsigned*)&Bb[br*SAPITCH + kbx + 2*t + 8];
            }
            #pragma unroll
            for (int mi = 0; mi < 4; mi++)
                #pragma unroll
                for (int nj = 0; nj < 4; nj++)
                    mma16816(acc[mi][nj], afr[mi], bfr[nj]);
        }
        __syncthreads();
    }

    #pragma unroll
    for (int nj = 0; nj < 4; nj++) {
        int col = n0 + wn + nj*8 + 2*t;
        float bv0 = __ldg(&d_bvec[col]), bv1 = __ldg(&d_bvec[col+1]);
        #pragma unroll
        for (int mi = 0; mi < 4; mi++) {
            acc[mi][nj][0] += bv0; acc[mi][nj][1] += bv1;
            acc[mi][nj][2] += bv0; acc[mi][nj][3] += bv1;
        }
    }

    float pel[4][2], per_[4][2];
    #pragma unroll
    for (int mi = 0; mi < 4; mi++) { pel[mi][0]=pel[mi][1]=per_[mi][0]=per_[mi][1]=0.f; }
    #pragma unroll
    for (int mi = 0; mi < 4; mi++)
        #pragma unroll
        for (int nj = 0; nj < 4; nj++) {
            int col = n0 + wn + nj*8 + 2*t;
            float al0 = __ldg(&attn_l[col]), al1 = __ldg(&attn_l[col+1]);
            float ar0 = __ldg(&attn_r[col]), ar1 = __ldg(&attn_r[col+1]);
            pel[mi][0]  += acc[mi][nj][0]*al0 + acc[mi][nj][1]*al1;
            pel[mi][1]  += acc[mi][nj][2]*al0 + acc[mi][nj][3]*al1;
            per_[mi][0] += acc[mi][nj][0]*ar0 + acc[mi][nj][1]*ar1;
            per_[mi][1] += acc[mi][nj][2]*ar0 + acc[mi][nj][3]*ar1;
        }
    #pragma unroll
    for (int mi = 0; mi < 4; mi++)
        #pragma unroll
        for (int h2 = 0; h2 < 2; h2++) {
            pel[mi][h2]  += __shfl_xor_sync(0xffffffffu, pel[mi][h2], 1);
            pel[mi][h2]  += __shfl_xor_sync(0xffffffffu, pel[mi][h2], 2);
            per_[mi][h2] += __shfl_xor_sync(0xffffffffu, per_[mi][h2], 1);
            per_[mi][h2] += __shfl_xor_sync(0xffffffffu, per_[mi][h2], 2);
        }
    int head = n0 >> 8;
    if (t == 0) {
        #pragma unroll
        for (int mi = 0; mi < 4; mi++) {
            int r0 = m0 + wm + mi*16 + g;
            if (r0 < NN)     { atomicAdd(&d_el[r0*4 + head], pel[mi][0]);
                               atomicAdd(&d_er[r0*4 + head], per_[mi][0]); }
            if (r0 + 8 < NN) { atomicAdd(&d_el[(r0+8)*4 + head], pel[mi][1]);
                               atomicAdd(&d_er[(r0+8)*4 + head], per_[mi][1]); }
        }
    }

    #pragma unroll
    for (int mi = 0; mi < 4; mi++) {
        int r0 = m0 + wm + mi*16 + g;
        #pragma unroll
        for (int nj = 0; nj < 4; nj++) {
            int col = n0 + wn + nj*8 + 2*t;
            if (r0 < NN)
                *(__half2*)&d_hh[(size_t)r0*HF + col] =
                    __float22half2_rn(make_float2(acc[mi][nj][0], acc[mi][nj][1]));
            if (r0 + 8 < NN)
                *(__half2*)&d_hh[(size_t)(r0+8)*HF + col] =
                    __float22half2_rn(make_float2(acc[mi][nj][2], acc[mi][nj][3]));
        }
    }
}

// ---------------- CSR build ----------------
__global__ void k_count(const int* __restrict__ dst) {
    int e = blockIdx.x * blockDim.x + threadIdx.x;
    if (e < EE) atomicAdd(&d_counts[dst[e]], 1);
}

__global__ __launch_bounds__(1024) void k_scan() {
    __shared__ int part[1024];
    int tid = threadIdx.x;
    int beg = tid * 20, end = min(beg + 20, NN);
    int s = 0;
    for (int i = beg; i < end; i++) s += d_counts[i];
    part[tid] = s;
    __syncthreads();
    for (int off = 1; off < 1024; off <<= 1) {
        int v = 0;
        if (tid >= off) v = part[tid - off];
        __syncthreads();
        if (tid >= off) part[tid] += v;
        __syncthreads();
    }
    int run = (tid == 0) ? 0 : part[tid - 1];
    for (int i = beg; i < end; i++) {
        d_rowstart[i] = run; d_wptr[i] = run;
        run += d_counts[i];
    }
    if (tid == 1023) d_rowstart[NN] = run;
}

__global__ void k_fill(const int* __restrict__ src, const int* __restrict__ dst) {
    int e = blockIdx.x * blockDim.x + threadIdx.x;
    if (e < EE) {
        int p = atomicAdd(&d_wptr[dst[e]], 1);
        d_colsrc[p] = src[e];
    }
}

// ---------------- GAT aggregation (fp16 gather) ----------------
__device__ __forceinline__ float lrelu(float x) { return x > 0.f ? x : SLOPE * x; }

__global__ __launch_bounds__(256) void k_agg(const float* __restrict__ bias) {
    int n = (blockIdx.x * blockDim.x + threadIdx.x) >> 5;
    int lane = threadIdx.x & 31;
    if (n >= NN) return;
    int beg = d_rowstart[n], end = d_rowstart[n+1];
    float er0 = d_er[n*4+0], er1 = d_er[n*4+1], er2 = d_er[n*4+2], er3 = d_er[n*4+3];

    float e0[4], e1[4], e2[4], e3[4];
    #pragma unroll
    for (int s = 0; s < 4; s++) {
        int j = beg + s*32 + lane;
        if (j < end) {
            int sc = d_colsrc[j];
            e0[s] = lrelu(d_el[sc*4+0] + er0);
            e1[s] = lrelu(d_el[sc*4+1] + er1);
            e2[s] = lrelu(d_el[sc*4+2] + er2);
            e3[s] = lrelu(d_el[sc*4+3] + er3);
        } else { e0[s] = e1[s] = e2[s] = e3[s] = -1e30f; }
    }
    float m0 = -1e30f, m1 = -1e30f, m2 = -1e30f, m3 = -1e30f;
    #pragma unroll
    for (int s = 0; s < 4; s++) {
        m0 = fmaxf(m0, e0[s]); m1 = fmaxf(m1, e1[s]);
        m2 = fmaxf(m2, e2[s]); m3 = fmaxf(m3, e3[s]);
    }
    #pragma unroll
    for (int off = 16; off; off >>= 1) {
        m0 = fmaxf(m0, __shfl_xor_sync(0xffffffffu, m0, off));
        m1 = fmaxf(m1, __shfl_xor_sync(0xffffffffu, m1, off));
        m2 = fmaxf(m2, __shfl_xor_sync(0xffffffffu, m2, off));
        m3 = fmaxf(m3, __shfl_xor_sync(0xffffffffu, m3, off));
    }
    float s0 = 0.f, s1 = 0.f, s2 = 0.f, s3 = 0.f;
    #pragma unroll
    for (int s = 0; s < 4; s++) {
        e0[s] = expf(e0[s] - m0); s0 += e0[s];
        e1[s] = expf(e1[s] - m1); s1 += e1[s];
        e2[s] = expf(e2[s] - m2); s2 += e2[s];
        e3[s] = expf(e3[s] - m3); s3 += e3[s];
    }
    #pragma unroll
    for (int off = 16; off; off >>= 1) {
        s0 += __shfl_xor_sync(0xffffffffu, s0, off);
        s1 += __shfl_xor_sync(0xffffffffu, s1, off);
        s2 += __shfl_xor_sync(0xffffffffu, s2, off);
        s3 += __shfl_xor_sync(0xffffffffu, s3, off);
    }
    float i0 = s0 > 0.f ? 1.f/s0 : 0.f;
    float i1 = s1 > 0.f ? 1.f/s1 : 0.f;
    float i2 = s2 > 0.f ? 1.f/s2 : 0.f;
    float i3 = s3 > 0.f ? 1.f/s3 : 0.f;
    #pragma unroll
    for (int s = 0; s < 4; s++) { e0[s] *= i0; e1[s] *= i1; e2[s] *= i2; e3[s] *= i3; }

    float acc[4][8];
    #pragma unroll
    for (int j = 0; j < 4; j++)
        #pragma unroll
        for (int e = 0; e < 8; e++) acc[j][e] = 0.f;

    #pragma unroll
    for (int s = 0; s < 4; s++) {
        int base = beg + s*32;
        int lim = end - base;
        if (lim <= 0) break;
        if (lim > 32) lim = 32;
        for (int u = 0; u < lim; u++) {
            int sc = d_colsrc[base + u];
            float wj[4];
            wj[0] = __shfl_sync(0xffffffffu, e0[s], u);
            wj[1] = __shfl_sync(0xffffffffu, e1[s], u);
            wj[2] = __shfl_sync(0xffffffffu, e2[s], u);
            wj[3] = __shfl_sync(0xffffffffu, e3[s], u);
            const uint4* hp = (const uint4*)&d_hh[(size_t)sc*HF];
            #pragma unroll
            for (int j = 0; j < 4; j++) {
                uint4 v = hp[j*32 + lane];
                float w = wj[j];
                float a, b;
                h2f(v.x, a, b); acc[j][0] += w*a; acc[j][1] += w*b;
                h2f(v.y, a, b); acc[j][2] += w*a; acc[j][3] += w*b;
                h2f(v.z, a, b); acc[j][4] += w*a; acc[j][5] += w*b;
                h2f(v.w, a, b); acc[j][6] += w*a; acc[j][7] += w*b;
            }
        }
    }
    #pragma unroll
    for (int j = 0; j < 4; j++) {
        int f0 = j*256 + lane*8;
        float4 b0 = __ldg((const float4*)&bias[f0]);
        float4 b1 = __ldg((const float4*)&bias[f0+4]);
        float4 v0 = make_float4(fmaxf(acc[j][0]+b0.x,0.f), fmaxf(acc[j][1]+b0.y,0.f),
                                fmaxf(acc[j][2]+b0.z,0.f), fmaxf(acc[j][3]+b0.w,0.f));
        float4 v1 = make_float4(fmaxf(acc[j][4]+b1.x,0.f), fmaxf(acc[j][5]+b1.y,0.f),
                                fmaxf(acc[j][6]+b1.z,0.f), fmaxf(acc[j][7]+b1.w,0.f));
        *(float4*)&d_rst[(size_t)n*HF + f0]     = v0;
        *(float4*)&d_rst[(size_t)n*HF + f0 + 4] = v1;
    }
}

// ---------------- bn1 stats ----------------
__global__ __launch_bounds__(256) void k_bn1stats() {
    int f = blockIdx.x * 256 + threadIdx.x;
    int n0 = blockIdx.y * 500;
    float s = 0.f, q = 0.f;
    for (int n = n0; n < n0 + 500; n++) {
        float v = d_rst[(size_t)n*HF + f];
        s += v; q += v*v;
    }
    atomicAdd(&d_bn1sum[f], s);
    atomicAdd(&d_bn1sum[1024 + f], q);
}

__global__ void k_bnfin1(const float* __restrict__ bn1g, const float* __restrict__ bn1b) {
    int f = blockIdx.x * 256 + threadIdx.x;
    if (f < 1024) {
        float invN = 1.f/(float)NN;
        float mean = d_bn1sum[f]*invN;
        float var  = d_bn1sum[1024+f]*invN - mean*mean;
        float a = bn1g[f]*rsqrtf(var + BEPS);
        d_ssc[f] = a; d_ssh[f] = bn1b[f] - mean*a;
    }
}

// ---------------- gated2 im2col pack (fp16, bn1 apply fused) ----------------
__global__ __launch_bounds__(256) void k_g2_pack() {
    int idx = blockIdx.x * 256 + threadIdx.x;
    int m = idx >> 7, ci = idx & 127;
    int n = m >> 3, t = m & 7;
    int f = ci*8 + t;
    const float* rr = &d_rst[(size_t)n*HF];
    float x0 = rr[f]*__ldg(&d_ssc[f]) + __ldg(&d_ssh[f]);
    float xm = (t > 0) ? rr[f-1]*__ldg(&d_ssc[f-1]) + __ldg(&d_ssh[f-1]) : 0.f;
    float xp = (t < 7) ? rr[f+1]*__ldg(&d_ssc[f+1]) + __ldg(&d_ssh[f+1]) : 0.f;
    size_t ab = (size_t)m*KA2H + ci*3;
    d_ai2h[ab+0] = __float2half(xm);
    d_ai2h[ab+1] = __float2half(x0);
    d_ai2h[ab+2] = __float2half(xp);
}

// ---------------- gated2 B pack (fp16) ----------------
__global__ void k_packB2(const float* __restrict__ w1, const float* __restrict__ w2,
                         const float* __restrict__ w3) {
    int i = blockIdx.x * 256 + threadIdx.x;
    if (i < 12288) {
        int co = i / 384, r = i % 384;
        d_bp2h[(co)*KA2H + r]    = __float2half(w1[i]);
        d_bp2h[(32+co)*KA2H + r] = __float2half(w2[i]);
        d_bp2h[(64+co)*KA2H + r] = __float2half(w3[i]);
    }
}

// ---------------- gated2 GEMM (fp16, N=96, K=384) + gating epilogue ----------
__global__ __launch_bounds__(256) void k_gemm_g2(
    const float* __restrict__ b1, const float* __restrict__ b2,
    const float* __restrict__ b3)
{
    extern __shared__ __align__(16) char gsm[];
    __half* As = (__half*)gsm;                     // [2][128*72]
    __half* Bs = As + 2*128*SAPITCH;               // [2][96*72]
    int tid = threadIdx.x;
    int m0 = blockIdx.x * 128;
    int w = tid >> 5, lane = tid & 31;
    int wm = (w >> 2) * 64, wn = (w & 3) * 24;
    int g = lane >> 2, t = lane & 3;
    uint32_t sA = (uint32_t)__cvta_generic_to_shared(As);
    uint32_t sB = (uint32_t)__cvta_generic_to_shared(Bs);

    float acc[4][3][4];
    #pragma unroll
    for (int i = 0; i < 4; i++)
        #pragma unroll
        for (int j = 0; j < 3; j++)
            #pragma unroll
            for (int q = 0; q < 4; q++) acc[i][j][q] = 0.f;

    int row4 = tid >> 3, ci4 = tid & 7;

    #pragma unroll
    for (int r = 0; r < 4; r++) {
        int row = row4 + r*32;
        cpasync16(sA + (row*SAPITCH + ci4*8)*2, &d_ai2h[(size_t)(m0 + row)*KA2H + ci4*8]);
        if (r < 3)
            cpasync16(sB + (row*SAPITCH + ci4*8)*2, &d_bp2h[row*KA2H + ci4*8]);
    }
    asm volatile("cp.async.commit_group;");

    for (int it = 0; it < 6; it++) {
        if (it < 5) {
            int k0 = (it + 1) * 64;
            int buf = (it + 1) & 1;
            #pragma unroll
            for (int r = 0; r < 4; r++) {
                int row = row4 + r*32;
                cpasync16(sA + (buf*128*SAPITCH + row*SAPITCH + ci4*8)*2,
                          &d_ai2h[(size_t)(m0 + row)*KA2H + k0 + ci4*8]);
                if (r < 3)
                    cpasync16(sB + (buf*96*SAPITCH + row*SAPITCH + ci4*8)*2,
                              &d_bp2h[row*KA2H + k0 + ci4*8]);
            }
            asm volatile("cp.async.commit_group;");
            asm volatile("cp.async.wait_group 1;");
        } else {
            asm volatile("cp.async.wait_group 0;");
        }
        __syncthreads();
        const __half* Ab = As + (it & 1)*128*SAPITCH;
        const __half* Bb = Bs + (it & 1)*96*SAPITCH;
        #pragma unroll
        for (int kk = 0; kk < 4; kk++) {
            int kbx = kk * 16;
            unsigned afr[4][4];
            #pragma unroll
            for (int mi = 0; mi < 4; mi++) {
                int r0 = wm + mi*16 + g;
                afr[mi][0] = *(const unsigned*)&Ab[r0      *SAPITCH + kbx + 2*t];
                afr[mi][1] = *(const unsigned*)&Ab[(r0 + 8)*SAPITCH + kbx + 2*t];
                afr[mi][2] = *(const unsigned*)&Ab[r0      *SAPITCH + kbx + 2*t + 8];
                afr[mi][3] = *(const unsigned*)&Ab[(r0 + 8)*SAPITCH + kbx + 2*t + 8];
            }
            unsigned bfr[3][2];
            #pragma unroll
            for (int nj = 0; nj < 3; nj++) {
                int br = wn + nj*8 + g;
                bfr[nj][0] = *(const unsigned*)&Bb[br*SAPITCH + kbx + 2*t];
                bfr[nj][1] = *(const unsigned*)&Bb[br*SAPITCH + kbx + 2*t + 8];
            }
            #pragma unroll
            for (int mi = 0; mi < 4; mi++)
                #pragma unroll
                for (int nj = 0; nj < 3; nj++)
                    mma16816h(acc[mi][nj], afr[mi], bfr[nj]);
        }
        __syncthreads();
    }

    float* sm = (float*)gsm;
    float* sstats = sm + 128*132;
    #pragma unroll
    for (int mi = 0; mi < 4; mi++) {
        int r0 = wm + mi*16 + g;
        #pragma unroll
        for (int nj = 0; nj < 3; nj++) {
            int col = wn + nj*8 + 2*t;
            *(float2*)&sm[r0*132 + col]     = make_float2(acc[mi][nj][0], acc[mi][nj][1]);
            *(float2*)&sm[(r0+8)*132 + col] = make_float2(acc[mi][nj][2], acc[mi][nj][3]);
        }
    }
    if (tid < 64) sstats[tid] = 0.f;
    __syncthreads();

    int nb = m0 >> 3;
    float B1 = b1[lane], B2 = b2[lane], B3 = b3[lane];
    float s = 0.f, q = 0.f;
    #pragma unroll
    for (int rep = 0; rep < 2; rep++) {
        int nl = rep*8 + w;
        int n = nb + nl;
        float g8[8];
        #pragma unroll
        for (int tt = 0; tt < 8; tt++) {
            const float* rw = &sm[(nl*8 + tt)*132];
            float a1 = rw[lane] + B1, a2 = rw[lane+32] + B2, a3 = rw[lane+64] + B3;
            float gg = a1*(1.f/(1.f+expf(-a2))) + a3;
            gg = fmaxf(gg, 0.f);
            g8[tt] = gg;
            s += gg; q += gg*gg;
        }
        *(float4*)&d_xn[n*256 + lane*8]     = make_float4(g8[0],g8[1],g8[2],g8[3]);
        *(float4*)&d_xn[n*256 + lane*8 + 4] = make_float4(g8[4],g8[5],g8[6],g8[7]);
    }
    atomicAdd(&sstats[lane], s);
    atomicAdd(&sstats[32+lane], q);
    __syncthreads();
    if (tid < 32) {
        atomicAdd(&d_bn2sum[tid],    sstats[tid]);
        atomicAdd(&d_bn2sum[32+tid], sstats[32+tid]);
    }
}

// ---------------- final ----------------
__global__ void k_out(float* __restrict__ out, const float* __restrict__ bn2g,
                      const float* __restrict__ bn2b) {
    __shared__ float ssc[32], ssh[32];
    int tid = threadIdx.x;
    if (tid < 32) {
        float inv = 1.f/(float)(NN*TT);
        float mean = d_bn2sum[tid]*inv;
        float var  = d_bn2sum[32+tid]*inv - mean*mean;
        float a = bn2g[tid]*rsqrtf(var + BEPS);
        ssc[tid] = a; ssh[tid] = bn2b[tid] - mean*a;
    }
    __syncthreads();
    int base = blockIdx.x * 2048;
    for (int o = tid; o < 2048; o += 256) {
        int i = base + o;
        if (i < NN*CT) {
            int c = (i >> 3) & 31;
            float v = d_xn[i]*ssc[c] + ssh[c] + d_res[i];
            out[i] = v > 0.f ? v : 0.f;
        }
    }
}

// ---------------- launch ----------------
extern "C" void kernel_launch(void* const* d_in, const int* in_sizes, int n_in,
                              void* d_out, int out_size) {
    const float* X      = (const float*)d_in[0];
    const int*   src    = (const int*)  d_in[1];
    const int*   dst    = (const int*)  d_in[2];
    const float* rp_w   = (const float*)d_in[3];
    const float* rp_b   = (const float*)d_in[4];
    const float* g1w1   = (const float*)d_in[5];
    const float* g1b1   = (const float*)d_in[6];
    const float* g1w2   = (const float*)d_in[7];
    const float* g1b2   = (const float*)d_in[8];
    const float* g1w3   = (const float*)d_in[9];
    const float* g1b3   = (const float*)d_in[10];
    const float* bn0g   = (const float*)d_in[11];
    const float* bn0b   = (const float*)d_in[12];
    const float* gatw   = (const float*)d_in[13];
    const float* attnl  = (const float*)d_in[14];
    const float* attnr  = (const float*)d_in[15];
    const float* gatb   = (const float*)d_in[16];
    const float* bn1g   = (const float*)d_in[17];
    const float* bn1b   = (const float*)d_in[18];
    const float* g2w1   = (const float*)d_in[19];
    const float* g2b1   = (const float*)d_in[20];
    const float* g2w2   = (const float*)d_in[21];
    const float* g2b2   = (const float*)d_in[22];
    const float* g2w3   = (const float*)d_in[23];
    const float* g2b3   = (const float*)d_in[24];
    const float* bn2g   = (const float*)d_in[25];
    const float* bn2b   = (const float*)d_in[26];
    float* out = (float*)d_out;

    static cudaStream_t s2 = 0;
    static cudaEvent_t evF = 0, evJ = 0;
    static int inited = 0;
    if (!inited) {
        cudaFuncSetAttribute(k_gemm_front, cudaFuncAttributeMaxDynamicSharedMemorySize, 73728);
        cudaFuncSetAttribute(k_gemm_tc,    cudaFuncAttributeMaxDynamicSharedMemorySize, 73728);
        cudaFuncSetAttribute(k_gemm_g2,    cudaFuncAttributeMaxDynamicSharedMemorySize, 73728);
        cudaStreamCreateWithFlags(&s2, cudaStreamNonBlocking);
        cudaEventCreateWithFlags(&evF, cudaEventDisableTiming);
        cudaEventCreateWithFlags(&evJ, cudaEventDisableTiming);
        inited = 1;
    }

    void *p_b0, *p_b1, *p_b2, *p_cnt, *p_el, *p_er;
    cudaGetSymbolAddress(&p_b0, d_bn0sum);
    cudaGetSymbolAddress(&p_b1, d_bn1sum);
    cudaGetSymbolAddress(&p_b2, d_bn2sum);
    cudaGetSymbolAddress(&p_cnt, d_counts);
    cudaGetSymbolAddress(&p_el, d_el);
    cudaGetSymbolAddress(&p_er, d_er);

    cudaMemsetAsync(p_b0, 0, 64*sizeof(float));
    cudaMemsetAsync(p_b1, 0, 2048*sizeof(float));
    cudaMemsetAsync(p_b2, 0, 64*sizeof(float));
    cudaMemsetAsync(p_el, 0, NN*HH*sizeof(float));
    cudaMemsetAsync(p_er, 0, NN*HH*sizeof(float));

    // side stream: gated2 B pack + CSR build
    cudaEventRecord(evF, 0);
    cudaStreamWaitEvent(s2, evF, 0);
    k_packB2<<<48, 256, 0, s2>>>(g2w1, g2w2, g2w3);
    cudaMemsetAsync(p_cnt, 0, NN*sizeof(int), s2);
    k_count<<<(EE + 255)/256, 256, 0, s2>>>(dst);
    k_scan<<<1, 1024, 0, s2>>>();
    k_fill<<<(EE + 255)/256, 256, 0, s2>>>(src, dst);
    cudaEventRecord(evJ, s2);

    // front: im2col + GEMM (writes apk) + bn0 finalize
    k_packB1<<<16, 256>>>(g1w1, g1w2, g1w3, rp_w);
    k_front_pack<<<MM2*32/256, 256>>>(X);
    k_gemm_front<<<MM2/128, 256, 73728>>>(g1b1, g1b2, g1b3, rp_b);
    k_bnfin0<<<1, 32>>>(bn0g, bn0b);

    // GAT projection GEMM (bn0 folded into W)
    k_packB<<<(HF*256 + 255)/256, 256>>>(gatw);
    k_bvec<<<128, 256>>>(gatw);
    k_gemm_tc<<<dim3(MPAD/128, HF/128), 256, 73728>>>(attnl, attnr);

    cudaStreamWaitEvent(0, evJ, 0);
    k_agg<<<(NN*32 + 255)/256, 256>>>(gatb);
    k_bn1stats<<<dim3(4, 40), 256>>>();
    k_bnfin1<<<4, 256>>>(bn1g, bn1b);

    // gated2: fp16 im2col + fp16 GEMM + gating epilogue
    k_g2_pack<<<MM2*128/256, 256>>>();
    k_gemm_g2<<<MM2/128, 256, 73728>>>(g2b1, g2b2, g2b3);

    k_out<<<(NN*CT + 2047)/2048, 256>>>(out, bn2g, bn2b);
}

// round 16
// speedup vs baseline: 1.4462x; 1.2376x over previous
#include <cuda_runtime.h>
#include <cuda_fp16.h>
#include <math.h>
#include <stdint.h>

#define NN 20000
#define CC 32
#define TT 8
#define HH 4
#define FF 256
#define HF 1024
#define EE 320000
#define CT 256
#define BEPS 1e-5f
#define SLOPE 0.2f

#define MPAD 20096
#define KPH 256             // GAT GEMM K (fp16)
#define SAPITCH 72
#define MM2 160000
#define KA1H 96             // front im2col K (fp16)
#define FP1 104             // front smem pitch (halves)
#define KA2H 384

typedef unsigned long long ull;

// ---------------- scratch ----------------
__device__ float d_res[NN*CT];
__device__ float d_xn[NN*CT];
__device__ __half d_hh[(size_t)NN*HF];
__device__ float d_rst[NN*HF];
__device__ float d_el[NN*HH];
__device__ float d_er[NN*HH];
__device__ int   d_counts[NN];
__device__ int   d_rowstart[NN+1];
__device__ int   d_wptr[NN];
__device__ int   d_colsrc[EE];
__device__ float d_bn0sum[64];
__device__ float d_bn1sum[2048];
__device__ float d_bn2sum[64];
__device__ float d_ssc0[32];
__device__ float d_ssh0[32];
__device__ float d_bvec[1024];
__device__ float d_ssc[1024];
__device__ float d_ssh[1024];
__device__ __half d_apk[(size_t)MPAD*KPH];   // rows >= NN stay zero
__device__ __half d_bpk[(size_t)HF*KPH];
__device__ __half d_ai1[(size_t)MM2*KA1H];
__device__ __half d_ai2h[(size_t)MM2*KA2H];
__device__ __half d_bp1[128*KA1H];
__device__ __half d_bp2h[96*KA2H];

// ---------------- helpers ----------------
__device__ __forceinline__ void cpasync16(uint32_t saddr, const void* g) {
    asm volatile("cp.async.cg.shared.global [%0], [%1], 16;" :: "r"(saddr), "l"(g));
}
__device__ __forceinline__ void h2f(unsigned u, float& a, float& b) {
    __half2 h = *(__half2*)&u;
    float2 f = __half22float2(h);
    a = f.x; b = f.y;
}
__device__ __forceinline__ void mma16816h(float* c, const unsigned* a, const unsigned* b) {
    asm volatile(
        "mma.sync.aligned.m16n8k16.row.col.f32.f16.f16.f32 "
        "{%0,%1,%2,%3}, {%4,%5,%6,%7}, {%8,%9}, {%0,%1,%2,%3};\n"
        : "+f"(c[0]), "+f"(c[1]), "+f"(c[2]), "+f"(c[3])
        : "r"(a[0]), "r"(a[1]), "r"(a[2]), "r"(a[3]), "r"(b[0]), "r"(b[1]));
}

// ---------------- front im2col pack: X -> d_ai1 (fp16) ----------------
__global__ __launch_bounds__(256) void k_front_pack(const float* __restrict__ X) {
    int idx = blockIdx.x * 256 + threadIdx.x;
    int m = idx >> 5, ci = idx & 31;
    int n = m >> 3, t = m & 7;
    int base = n*256 + ci*8 + t;
    float x0 = X[base];
    float xm = (t > 0) ? X[base-1] : 0.f;
    float xp = (t < 7) ? X[base+1] : 0.f;
    size_t ab = (size_t)m*KA1H + ci*3;
    d_ai1[ab+0] = __float2half(xm);
    d_ai1[ab+1] = __float2half(x0);
    d_ai1[ab+2] = __float2half(xp);
}

// ---------------- front B pack (fp16) ----------------
__global__ void k_packB1(const float* __restrict__ w1, const float* __restrict__ w2,
                         const float* __restrict__ w3, const float* __restrict__ rp) {
    int i = blockIdx.x * 256 + threadIdx.x;
    if (i < 3072) {
        int co = i / 96, r = i % 96;
        d_bp1[(co)*KA1H + r]    = __float2half(w1[i]);
        d_bp1[(32+co)*KA1H + r] = __float2half(w2[i]);
        d_bp1[(64+co)*KA1H + r] = __float2half(w3[i]);
    } else if (i < 4096) {
        int j = i - 3072, co = j >> 5, ci = j & 31;
        d_bp1[(96+co)*KA1H + ci*3 + 1] = __float2half(rp[j]);
    }
}

// ---------------- front GEMM (fp16, K=96) + gating epilogue -------------------
__global__ __launch_bounds__(256) void k_gemm_front(
    const float* __restrict__ b1, const float* __restrict__ b2,
    const float* __restrict__ b3, const float* __restrict__ rpb)
{
    extern __shared__ __align__(16) char gsm[];
    __half* As = (__half*)gsm;                 // 128*104
    __half* Bs = As + 128*FP1;
    int tid = threadIdx.x;
    int m0 = blockIdx.x * 128;
    int w = tid >> 5, lane = tid & 31;
    int wm = (w >> 2) * 64, wn = (w & 3) * 32;
    int g = lane >> 2, t = lane & 3;
    uint32_t sA = (uint32_t)__cvta_generic_to_shared(As);
    uint32_t sB = (uint32_t)__cvta_generic_to_shared(Bs);

    float acc[4][4][4];
    #pragma unroll
    for (int i = 0; i < 4; i++)
        #pragma unroll
        for (int j = 0; j < 4; j++)
            #pragma unroll
            for (int q = 0; q < 4; q++) acc[i][j][q] = 0.f;

    // single-shot load: 128 rows x 96 halves = 12 chunks/row
    #pragma unroll
    for (int p = 0; p < 6; p++) {
        int l = tid + p*256;
        int row = l / 12, c = (l % 12) * 8;
        cpasync16(sA + (row*FP1 + c)*2, &d_ai1[(size_t)(m0+row)*KA1H + c]);
        cpasync16(sB + (row*FP1 + c)*2, &d_bp1[row*KA1H + c]);
    }
    asm volatile("cp.async.commit_group;");
    asm volatile("cp.async.wait_group 0;");
    __syncthreads();

    #pragma unroll
    for (int kk = 0; kk < 6; kk++) {
        int kbx = kk * 16;
        unsigned afr[4][4];
        #pragma unroll
        for (int mi = 0; mi < 4; mi++) {
            int r0 = wm + mi*16 + g;
            afr[mi][0] = *(const unsigned*)&As[r0    *FP1 + kbx + 2*t];
            afr[mi][1] = *(const unsigned*)&As[(r0+8)*FP1 + kbx + 2*t];
            afr[mi][2] = *(const unsigned*)&As[r0    *FP1 + kbx + 2*t + 8];
            afr[mi][3] = *(const unsigned*)&As[(r0+8)*FP1 + kbx + 2*t + 8];
        }
        unsigned bfr[4][2];
        #pragma unroll
        for (int nj = 0; nj < 4; nj++) {
            int br = wn + nj*8 + g;
            bfr[nj][0] = *(const unsigned*)&Bs[br*FP1 + kbx + 2*t];
            bfr[nj][1] = *(const unsigned*)&Bs[br*FP1 + kbx + 2*t + 8];
        }
        #pragma unroll
        for (int mi = 0; mi < 4; mi++)
            #pragma unroll
            for (int nj = 0; nj < 4; nj++)
                mma16816h(acc[mi][nj], afr[mi], bfr[nj]);
    }
    __syncthreads();

    float* sm = (float*)gsm;
    float* sstats = sm + 128*132;
    #pragma unroll
    for (int mi = 0; mi < 4; mi++) {
        int r0 = wm + mi*16 + g;
        #pragma unroll
        for (int nj = 0; nj < 4; nj++) {
            int col = wn + nj*8 + 2*t;
            *(float2*)&sm[r0*132 + col]     = make_float2(acc[mi][nj][0], acc[mi][nj][1]);
            *(float2*)&sm[(r0+8)*132 + col] = make_float2(acc[mi][nj][2], acc[mi][nj][3]);
        }
    }
    if (tid < 64) sstats[tid] = 0.f;
    __syncthreads();

    int nb = m0 >> 3;
    float B1 = b1[lane], B2 = b2[lane], B3 = b3[lane], BR = rpb[lane];
    float s = 0.f, q = 0.f;
    #pragma unroll
    for (int rep = 0; rep < 2; rep++) {
        int nl = rep*8 + w;
        int n = nb + nl;
        __half hbuf[8];
        float r8[8];
        #pragma unroll
        for (int tt = 0; tt < 8; tt++) {
            const float* rw = &sm[(nl*8 + tt)*132];
            float a1 = rw[lane] + B1, a2 = rw[lane+32] + B2;
            float a3 = rw[lane+64] + B3, rr = rw[lane+96] + BR;
            float gg = a1*(1.f/(1.f+expf(-a2))) + a3;
            gg = fmaxf(gg, 0.f);
            hbuf[tt] = __float2half(gg);
            r8[tt] = rr;
            s += gg; q += gg*gg;
        }
        *(uint4*)&d_apk[(size_t)n*KPH + lane*8] = *(uint4*)hbuf;
        *(float4*)&d_res[n*256 + lane*8]     = make_float4(r8[0],r8[1],r8[2],r8[3]);
        *(float4*)&d_res[n*256 + lane*8 + 4] = make_float4(r8[4],r8[5],r8[6],r8[7]);
    }
    atomicAdd(&sstats[lane], s);
    atomicAdd(&sstats[32+lane], q);
    __syncthreads();
    if (tid < 32) {
        atomicAdd(&d_bn0sum[tid],    sstats[tid]);
        atomicAdd(&d_bn0sum[32+tid], sstats[32+tid]);
    }
}

// ---------------- bn0 finalize ----------------
__global__ void k_bnfin0(const float* __restrict__ bn0g, const float* __restrict__ bn0b) {
    int t = threadIdx.x;
    if (t < 32) {
        float inv = 1.f/(float)(NN*TT);
        float mean = d_bn0sum[t]*inv;
        float var  = d_bn0sum[32+t]*inv - mean*mean;
        float a = bn0g[t]*rsqrtf(var + BEPS);
        d_ssc0[t] = a; d_ssh0[t] = bn0b[t] - mean*a;
    }
}

// ---------------- GAT B pack (fp16, bn0 scale folded) ----------------
__global__ void k_packB(const float* __restrict__ W) {
    int i = blockIdx.x * blockDim.x + threadIdx.x;
    if (i < HF*256) {
        int o = i >> 8, k = i & 255;
        d_bpk[(size_t)o*KPH + k] = __float2half(W[i] * __ldg(&d_ssc0[k >> 3]));
    }
}

// ---------------- bvec ----------------
__global__ void k_bvec(const float* __restrict__ W) {
    int o = blockIdx.x * 8 + (threadIdx.x >> 5);
    int lane = threadIdx.x & 31;
    float s = 0.f;
    for (int k = lane; k < 256; k += 32)
        s += __ldg(&d_ssh0[k >> 3]) * W[o*256 + k];
    #pragma unroll
    for (int off = 16; off; off >>= 1) s += __shfl_xor_sync(0xffffffffu, s, off);
    if (lane == 0) d_bvec[o] = s;
}

// ---------------- GAT GEMM (fp16, K=256) + bvec + el/er, fp16 h out ----------
__global__ __launch_bounds__(256) void k_gemm_tc(const float* __restrict__ attn_l,
                                                 const float* __restrict__ attn_r) {
    extern __shared__ __align__(16) char gsm[];
    __half* As = (__half*)gsm;                 // [2][128*72]
    __half* Bs = As + 2*128*SAPITCH;

    int tid = threadIdx.x;
    int m0 = blockIdx.x * 128, n0 = blockIdx.y * 128;
    int w = tid >> 5, lane = tid & 31;
    int wm = (w >> 2) * 64, wn = (w & 3) * 32;
    int g = lane >> 2, t = lane & 3;

    uint32_t sA = (uint32_t)__cvta_generic_to_shared(As);
    uint32_t sB = (uint32_t)__cvta_generic_to_shared(Bs);

    float acc[4][4][4];
    #pragma unroll
    for (int i = 0; i < 4; i++)
        #pragma unroll
        for (int j = 0; j < 4; j++)
            #pragma unroll
            for (int q = 0; q < 4; q++) acc[i][j][q] = 0.f;

    int row4 = tid >> 3, ci4 = tid & 7;

    #pragma unroll
    for (int r = 0; r < 4; r++) {
        int row = row4 + r*32;
        cpasync16(sA + (row*SAPITCH + ci4*8)*2, &d_apk[(size_t)(m0 + row)*KPH + ci4*8]);
        cpasync16(sB + (row*SAPITCH + ci4*8)*2, &d_bpk[(size_t)(n0 + row)*KPH + ci4*8]);
    }
    asm volatile("cp.async.commit_group;");

    for (int it = 0; it < 4; it++) {
        if (it < 3) {
            int k0 = (it + 1) * 64;
            int buf = (it + 1) & 1;
            #pragma unroll
            for (int r = 0; r < 4; r++) {
                int row = row4 + r*32;
                cpasync16(sA + (buf*128*SAPITCH + row*SAPITCH + ci4*8)*2,
                          &d_apk[(size_t)(m0 + row)*KPH + k0 + ci4*8]);
                cpasync16(sB + (buf*128*SAPITCH + row*SAPITCH + ci4*8)*2,
                          &d_bpk[(size_t)(n0 + row)*KPH + k0 + ci4*8]);
            }
            asm volatile("cp.async.commit_group;");
            asm volatile("cp.async.wait_group 1;");
        } else {
            asm volatile("cp.async.wait_group 0;");
        }
        __syncthreads();

        const __half* Ab = As + (it & 1)*128*SAPITCH;
        const __half* Bb = Bs + (it & 1)*128*SAPITCH;
        #pragma unroll
        for (int kk = 0; kk < 4; kk++) {
            int kbx = kk * 16;
            unsigned afr[4][4];
            #pragma unroll
            for (int mi = 0; mi < 4; mi++) {
                int r0 = wm + mi*16 + g;
                afr[mi][0] = *(const unsigned*)&Ab[r0      *SAPITCH + kbx + 2*t];
                afr[mi][1] = *(const unsigned*)&Ab[(r0 + 8)*SAPITCH + kbx + 2*t];
                afr[mi][2] = *(const unsigned*)&Ab[r0      *SAPITCH + kbx + 2*t + 8];
                afr[mi][3] = *(const unsigned*)&Ab[(r0 + 8)*SAPITCH + kbx + 2*t + 8];
            }
            unsigned bfr[4][2];
            #pragma unroll
            for (int nj = 0; nj < 4; nj++) {
                int br = wn + nj*8 + g;
                bfr[nj][0] = *(const unsigned*)&Bb[br*SAPITCH + kbx + 2*t];
                bfr[nj][1] = *(const unsigned*)&Bb[br*SAPITCH + kbx + 2*t + 8];
            }
            #pragma unroll
            for (int mi = 0; mi < 4; mi++)
                #pragma unroll
                for (int nj = 0; nj < 4; nj++)
                    mma16816h(acc[mi][nj], afr[mi], bfr[nj]);
        }
        __syncthreads();
    }

    #pragma unroll
    for (int nj = 0; nj < 4; nj++) {
        int col = n0 + wn + nj*8 + 2*t;
        float bv0 = __ldg(&d_bvec[col]), bv1 = __ldg(&d_bvec[col+1]);
        #pragma unroll
        for (int mi = 0; mi < 4; mi++) {
            acc[mi][nj][0] += bv0; acc[mi][nj][1] += bv1;
            acc[mi][nj][2] += bv0; acc[mi][nj][3] += bv1;
        }
    }

    float pel[4][2], per_[4][2];
    #pragma unroll
    for (int mi = 0; mi < 4; mi++) { pel[mi][0]=pel[mi][1]=per_[mi][0]=per_[mi][1]=0.f; }
    #pragma unroll
    for (int mi = 0; mi < 4; mi++)
        #pragma unroll
        for (int nj = 0; nj < 4; nj++) {
            int col = n0 + wn + nj*8 + 2*t;
            float al0 = __ldg(&attn_l[col]), al1 = __ldg(&attn_l[col+1]);
            float ar0 = __ldg(&attn_r[col]), ar1 = __ldg(&attn_r[col+1]);
            pel[mi][0]  += acc[mi][nj][0]*al0 + acc[mi][nj][1]*al1;
            pel[mi][1]  += acc[mi][nj][2]*al0 + acc[mi][nj][3]*al1;
            per_[mi][0] += acc[mi][nj][0]*ar0 + acc[mi][nj][1]*ar1;
            per_[mi][1] += acc[mi][nj][2]*ar0 + acc[mi][nj][3]*ar1;
        }
    #pragma unroll
    for (int mi = 0; mi < 4; mi++)
        #pragma unroll
        for (int h2 = 0; h2 < 2; h2++) {
            pel[mi][h2]  += __shfl_xor_sync(0xffffffffu, pel[mi][h2], 1);
            pel[mi][h2]  += __shfl_xor_sync(0xffffffffu, pel[mi][h2], 2);
            per_[mi][h2] += __shfl_xor_sync(0xffffffffu, per_[mi][h2], 1);
            per_[mi][h2] += __shfl_xor_sync(0xffffffffu, per_[mi][h2], 2);
        }
    int head = n0 >> 8;
    if (t == 0) {
        #pragma unroll
        for (int mi = 0; mi < 4; mi++) {
            int r0 = m0 + wm + mi*16 + g;
            if (r0 < NN)     { atomicAdd(&d_el[r0*4 + head], pel[mi][0]);
                               atomicAdd(&d_er[r0*4 + head], per_[mi][0]); }
            if (r0 + 8 < NN) { atomicAdd(&d_el[(r0+8)*4 + head], pel[mi][1]);
                               atomicAdd(&d_er[(r0+8)*4 + head], per_[mi][1]); }
        }
    }

    #pragma unroll
    for (int mi = 0; mi < 4; mi++) {
        int r0 = m0 + wm + mi*16 + g;
        #pragma unroll
        for (int nj = 0; nj < 4; nj++) {
            int col = n0 + wn + nj*8 + 2*t;
            if (r0 < NN)
                *(__half2*)&d_hh[(size_t)r0*HF + col] =
                    __float22half2_rn(make_float2(acc[mi][nj][0], acc[mi][nj][1]));
            if (r0 + 8 < NN)
                *(__half2*)&d_hh[(size_t)(r0+8)*HF + col] =
                    __float22half2_rn(make_float2(acc[mi][nj][2], acc[mi][nj][3]));
        }
    }
}

// ---------------- CSR build ----------------
__global__ void k_count(const int* __restrict__ dst) {
    int e = blockIdx.x * blockDim.x + threadIdx.x;
    if (e < EE) atomicAdd(&d_counts[dst[e]], 1);
}

__global__ __launch_bounds__(1024) void k_scan() {
    __shared__ int part[1024];
    int tid = threadIdx.x;
    int beg = tid * 20, end = min(beg + 20, NN);
    int s = 0;
    for (int i = beg; i < end; i++) s += d_counts[i];
    part[tid] = s;
    __syncthreads();
    for (int off = 1; off < 1024; off <<= 1) {
        int v = 0;
        if (tid >= off) v = part[tid - off];
        __syncthreads();
        if (tid >= off) part[tid] += v;
        __syncthreads();
    }
    int run = (tid == 0) ? 0 : part[tid - 1];
    for (int i = beg; i < end; i++) {
        d_rowstart[i] = run; d_wptr[i] = run;
        run += d_counts[i];
    }
    if (tid == 1023) d_rowstart[NN] = run;
}

__global__ void k_fill(const int* __restrict__ src, const int* __restrict__ dst) {
    int e = blockIdx.x * blockDim.x + threadIdx.x;
    if (e < EE) {
        int p = atomicAdd(&d_wptr[dst[e]], 1);
        d_colsrc[p] = src[e];
    }
}

// ---------------- GAT aggregation (fp16 gather) ----------------
__device__ __forceinline__ float lrelu(float x) { return x > 0.f ? x : SLOPE * x; }

__global__ __launch_bounds__(256) void k_agg(const float* __restrict__ bias) {
    int n = (blockIdx.x * blockDim.x + threadIdx.x) >> 5;
    int lane = threadIdx.x & 31;
    if (n >= NN) return;
    int beg = d_rowstart[n], end = d_rowstart[n+1];
    float er0 = d_er[n*4+0], er1 = d_er[n*4+1], er2 = d_er[n*4+2], er3 = d_er[n*4+3];

    float e0[4], e1[4], e2[4], e3[4];
    #pragma unroll
    for (int s = 0; s < 4; s++) {
        int j = beg + s*32 + lane;
        if (j < end) {
            int sc = d_colsrc[j];
            e0[s] = lrelu(d_el[sc*4+0] + er0);
            e1[s] = lrelu(d_el[sc*4+1] + er1);
            e2[s] = lrelu(d_el[sc*4+2] + er2);
            e3[s] = lrelu(d_el[sc*4+3] + er3);
        } else { e0[s] = e1[s] = e2[s] = e3[s] = -1e30f; }
    }
    float m0 = -1e30f, m1 = -1e30f, m2 = -1e30f, m3 = -1e30f;
    #pragma unroll
    for (int s = 0; s < 4; s++) {
        m0 = fmaxf(m0, e0[s]); m1 = fmaxf(m1, e1[s]);
        m2 = fmaxf(m2, e2[s]); m3 = fmaxf(m3, e3[s]);
    }
    #pragma unroll
    for (int off = 16; off; off >>= 1) {
        m0 = fmaxf(m0, __shfl_xor_sync(0xffffffffu, m0, off));
        m1 = fmaxf(m1, __shfl_xor_sync(0xffffffffu, m1, off));
        m2 = fmaxf(m2, __shfl_xor_sync(0xffffffffu, m2, off));
        m3 = fmaxf(m3, __shfl_xor_sync(0xffffffffu, m3, off));
    }
    float s0 = 0.f, s1 = 0.f, s2 = 0.f, s3 = 0.f;
    #pragma unroll
    for (int s = 0; s < 4; s++) {
        e0[s] = expf(e0[s] - m0); s0 += e0[s];
        e1[s] = expf(e1[s] - m1); s1 += e1[s];
        e2[s] = expf(e2[s] - m2); s2 += e2[s];
        e3[s] = expf(e3[s] - m3); s3 += e3[s];
    }
    #pragma unroll
    for (int off = 16; off; off >>= 1) {
        s0 += __shfl_xor_sync(0xffffffffu, s0, off);
        s1 += __shfl_xor_sync(0xffffffffu, s1, off);
        s2 += __shfl_xor_sync(0xffffffffu, s2, off);
        s3 += __shfl_xor_sync(0xffffffffu, s3, off);
    }
    float i0 = s0 > 0.f ? 1.f/s0 : 0.f;
    float i1 = s1 > 0.f ? 1.f/s1 : 0.f;
    float i2 = s2 > 0.f ? 1.f/s2 : 0.f;
    float i3 = s3 > 0.f ? 1.f/s3 : 0.f;
    #pragma unroll
    for (int s = 0; s < 4; s++) { e0[s] *= i0; e1[s] *= i1; e2[s] *= i2; e3[s] *= i3; }

    float acc[4][8];
    #pragma unroll
    for (int j = 0; j < 4; j++)
        #pragma unroll
        for (int e = 0; e < 8; e++) acc[j][e] = 0.f;

    #pragma unroll
    for (int s = 0; s < 4; s++) {
        int base = beg + s*32;
        int lim = end - base;
        if (lim <= 0) break;
        if (lim > 32) lim = 32;
        for (int u = 0; u < lim; u++) {
            int sc = d_colsrc[base + u];
            float wj[4];
            wj[0] = __shfl_sync(0xffffffffu, e0[s], u);
            wj[1] = __shfl_sync(0xffffffffu, e1[s], u);
            wj[2] = __shfl_sync(0xffffffffu, e2[s], u);
            wj[3] = __shfl_sync(0xffffffffu, e3[s], u);
            const uint4* hp = (const uint4*)&d_hh[(size_t)sc*HF];
            #pragma unroll
            for (int j = 0; j < 4; j++) {
                uint4 v = hp[j*32 + lane];
                float w = wj[j];
                float a, b;
                h2f(v.x, a, b); acc[j][0] += w*a; acc[j][1] += w*b;
                h2f(v.y, a, b); acc[j][2] += w*a; acc[j][3] += w*b;
                h2f(v.z, a, b); acc[j][4] += w*a; acc[j][5] += w*b;
                h2f(v.w, a, b); acc[j][6] += w*a; acc[j][7] += w*b;
            }
        }
    }
    #pragma unroll
    for (int j = 0; j < 4; j++) {
        int f0 = j*256 + lane*8;
        float4 b0 = __ldg((const float4*)&bias[f0]);
        float4 b1 = __ldg((const float4*)&bias[f0+4]);
        float4 v0 = make_float4(fmaxf(acc[j][0]+b0.x,0.f), fmaxf(acc[j][1]+b0.y,0.f),
                                fmaxf(acc[j][2]+b0.z,0.f), fmaxf(acc[j][3]+b0.w,0.f));
        float4 v1 = make_float4(fmaxf(acc[j][4]+b1.x,0.f), fmaxf(acc[j][5]+b1.y,0.f),
                                fmaxf(acc[j][6]+b1.z,0.f), fmaxf(acc[j][7]+b1.w,0.f));
        *(float4*)&d_rst[(size_t)n*HF + f0]     = v0;
        *(float4*)&d_rst[(size_t)n*HF + f0 + 4] = v1;
    }
}

// ---------------- bn1 stats ----------------
__global__ __launch_bounds__(256) void k_bn1stats() {
    int f = blockIdx.x * 256 + threadIdx.x;
    int n0 = blockIdx.y * 500;
    float s = 0.f, q = 0.f;
    for (int n = n0; n < n0 + 500; n++) {
        float v = d_rst[(size_t)n*HF + f];
        s += v; q += v*v;
    }
    atomicAdd(&d_bn1sum[f], s);
    atomicAdd(&d_bn1sum[1024 + f], q);
}

__global__ void k_bnfin1(const float* __restrict__ bn1g, const float* __restrict__ bn1b) {
    int f = blockIdx.x * 256 + threadIdx.x;
    if (f < 1024) {
        float invN = 1.f/(float)NN;
        float mean = d_bn1sum[f]*invN;
        float var  = d_bn1sum[1024+f]*invN - mean*mean;
        float a = bn1g[f]*rsqrtf(var + BEPS);
        d_ssc[f] = a; d_ssh[f] = bn1b[f] - mean*a;
    }
}

// ---------------- gated2 im2col pack (fp16, bn1 apply fused) ----------------
__global__ __launch_bounds__(256) void k_g2_pack() {
    int idx = blockIdx.x * 256 + threadIdx.x;
    int m = idx >> 7, ci = idx & 127;
    int n = m >> 3, t = m & 7;
    int f = ci*8 + t;
    const float* rr = &d_rst[(size_t)n*HF];
    float x0 = rr[f]*__ldg(&d_ssc[f]) + __ldg(&d_ssh[f]);
    float xm = (t > 0) ? rr[f-1]*__ldg(&d_ssc[f-1]) + __ldg(&d_ssh[f-1]) : 0.f;
    float xp = (t < 7) ? rr[f+1]*__ldg(&d_ssc[f+1]) + __ldg(&d_ssh[f+1]) : 0.f;
    size_t ab = (size_t)m*KA2H + ci*3;
    d_ai2h[ab+0] = __float2half(xm);
    d_ai2h[ab+1] = __float2half(x0);
    d_ai2h[ab+2] = __float2half(xp);
}

// ---------------- gated2 B pack (fp16) ----------------
__global__ void k_packB2(const float* __restrict__ w1, const float* __restrict__ w2,
                         const float* __restrict__ w3) {
    int i = blockIdx.x * 256 + threadIdx.x;
    if (i < 12288) {
        int co = i / 384, r = i % 384;
        d_bp2h[(co)*KA2H + r]    = __float2half(w1[i]);
        d_bp2h[(32+co)*KA2H + r] = __float2half(w2[i]);
        d_bp2h[(64+co)*KA2H + r] = __float2half(w3[i]);
    }
}

// ---------------- gated2 GEMM (fp16, N=96, K=384) + gating epilogue ----------
__global__ __launch_bounds__(256) void k_gemm_g2(
    const float* __restrict__ b1, const float* __restrict__ b2,
    const float* __restrict__ b3)
{
    extern __shared__ __align__(16) char gsm[];
    __half* As = (__half*)gsm;                 // [2][128*72]
    __half* Bs = As + 2*128*SAPITCH;           // [2][96*72]
    int tid = threadIdx.x;
    int m0 = blockIdx.x * 128;
    int w = tid >> 5, lane = tid & 31;
    int wm = (w >> 2) * 64, wn = (w & 3) * 24;
    int g = lane >> 2, t = lane & 3;
    uint32_t sA = (uint32_t)__cvta_generic_to_shared(As);
    uint32_t sB = (uint32_t)__cvta_generic_to_shared(Bs);

    float acc[4][3][4];
    #pragma unroll
    for (int i = 0; i < 4; i++)
        #pragma unroll
        for (int j = 0; j < 3; j++)
            #pragma unroll
            for (int q = 0; q < 4; q++) acc[i][j][q] = 0.f;

    int row4 = tid >> 3, ci4 = tid & 7;

    #pragma unroll
    for (int r = 0; r < 4; r++) {
        int row = row4 + r*32;
        cpasync16(sA + (row*SAPITCH + ci4*8)*2, &d_ai2h[(size_t)(m0 + row)*KA2H + ci4*8]);
        if (r < 3)
            cpasync16(sB + (row*SAPITCH + ci4*8)*2, &d_bp2h[row*KA2H + ci4*8]);
    }
    asm volatile("cp.async.commit_group;");

    for (int it = 0; it < 6; it++) {
        if (it < 5) {
            int k0 = (it + 1) * 64;
            int buf = (it + 1) & 1;
            #pragma unroll
            for (int r = 0; r < 4; r++) {
                int row = row4 + r*32;
                cpasync16(sA + (buf*128*SAPITCH + row*SAPITCH + ci4*8)*2,
                          &d_ai2h[(size_t)(m0 + row)*KA2H + k0 + ci4*8]);
                if (r < 3)
                    cpasync16(sB + (buf*96*SAPITCH + row*SAPITCH + ci4*8)*2,
                              &d_bp2h[row*KA2H + k0 + ci4*8]);
            }
            asm volatile("cp.async.commit_group;");
            asm volatile("cp.async.wait_group 1;");
        } else {
            asm volatile("cp.async.wait_group 0;");
        }
        __syncthreads();
        const __half* Ab = As + (it & 1)*128*SAPITCH;
        const __half* Bb = Bs + (it & 1)*96*SAPITCH;
        #pragma unroll
        for (int kk = 0; kk < 4; kk++) {
            int kbx = kk * 16;
            unsigned afr[4][4];
            #pragma unroll
            for (int mi = 0; mi < 4; mi++) {
                int r0 = wm + mi*16 + g;
                afr[mi][0] = *(const unsigned*)&Ab[r0      *SAPITCH + kbx + 2*t];
                afr[mi][1] = *(const unsigned*)&Ab[(r0 + 8)*SAPITCH + kbx + 2*t];
                afr[mi][2] = *(const unsigned*)&Ab[r0      *SAPITCH + kbx + 2*t + 8];
                afr[mi][3] = *(const unsigned*)&Ab[(r0 + 8)*SAPITCH + kbx + 2*t + 8];
            }
            unsigned bfr[3][2];
            #pragma unroll
            for (int nj = 0; nj < 3; nj++) {
                int br = wn + nj*8 + g;
                bfr[nj][0] = *(const unsigned*)&Bb[br*SAPITCH + kbx + 2*t];
                bfr[nj][1] = *(const unsigned*)&Bb[br*SAPITCH + kbx + 2*t + 8];
            }
            #pragma unroll
            for (int mi = 0; mi < 4; mi++)
                #pragma unroll
                for (int nj = 0; nj < 3; nj++)
                    mma16816h(acc[mi][nj], afr[mi], bfr[nj]);
        }
        __syncthreads();
    }

    float* sm = (float*)gsm;
    float* sstats = sm + 128*132;
    #pragma unroll
    for (int mi = 0; mi < 4; mi++) {
        int r0 = wm + mi*16 + g;
        #pragma unroll
        for (int nj = 0; nj < 3; nj++) {
            int col = wn + nj*8 + 2*t;
            *(float2*)&sm[r0*132 + col]     = make_float2(acc[mi][nj][0], acc[mi][nj][1]);
            *(float2*)&sm[(r0+8)*132 + col] = make_float2(acc[mi][nj][2], acc[mi][nj][3]);
        }
    }
    if (tid < 64) sstats[tid] = 0.f;
    __syncthreads();

    int nb = m0 >> 3;
    float B1 = b1[lane], B2 = b2[lane], B3 = b3[lane];
    float s = 0.f, q = 0.f;
    #pragma unroll
    for (int rep = 0; rep < 2; rep++) {
        int nl = rep*8 + w;
        int n = nb + nl;
        float g8[8];
        #pragma unroll
        for (int tt = 0; tt < 8; tt++) {
            const float* rw = &sm[(nl*8 + tt)*132];
            float a1 = rw[lane] + B1, a2 = rw[lane+32] + B2, a3 = rw[lane+64] + B3;
            float gg = a1*(1.f/(1.f+expf(-a2))) + a3;
            gg = fmaxf(gg, 0.f);
            g8[tt] = gg;
            s += gg; q += gg*gg;
        }
        *(float4*)&d_xn[n*256 + lane*8]     = make_float4(g8[0],g8[1],g8[2],g8[3]);
        *(float4*)&d_xn[n*256 + lane*8 + 4] = make_float4(g8[4],g8[5],g8[6],g8[7]);
    }
    atomicAdd(&sstats[lane], s);
    atomicAdd(&sstats[32+lane], q);
    __syncthreads();
    if (tid < 32) {
        atomicAdd(&d_bn2sum[tid],    sstats[tid]);
        atomicAdd(&d_bn2sum[32+tid], sstats[32+tid]);
    }
}

// ---------------- final ----------------
__global__ void k_out(float* __restrict__ out, const float* __restrict__ bn2g,
                      const float* __restrict__ bn2b) {
    __shared__ float ssc[32], ssh[32];
    int tid = threadIdx.x;
    if (tid < 32) {
        float inv = 1.f/(float)(NN*TT);
        float mean = d_bn2sum[tid]*inv;
        float var  = d_bn2sum[32+tid]*inv - mean*mean;
        float a = bn2g[tid]*rsqrtf(var + BEPS);
        ssc[tid] = a; ssh[tid] = bn2b[tid] - mean*a;
    }
    __syncthreads();
    int base = blockIdx.x * 2048;
    for (int o = tid; o < 2048; o += 256) {
        int i = base + o;
        if (i < NN*CT) {
            int c = (i >> 3) & 31;
            float v = d_xn[i]*ssc[c] + ssh[c] + d_res[i];
            out[i] = v > 0.f ? v : 0.f;
        }
    }
}

// ---------------- launch ----------------
extern "C" void kernel_launch(void* const* d_in, const int* in_sizes, int n_in,
                              void* d_out, int out_size) {
    const float* X      = (const float*)d_in[0];
    const int*   src    = (const int*)  d_in[1];
    const int*   dst    = (const int*)  d_in[2];
    const float* rp_w   = (const float*)d_in[3];
    const float* rp_b   = (const float*)d_in[4];
    const float* g1w1   = (const float*)d_in[5];
    const float* g1b1   = (const float*)d_in[6];
    const float* g1w2   = (const float*)d_in[7];
    const float* g1b2   = (const float*)d_in[8];
    const float* g1w3   = (const float*)d_in[9];
    const float* g1b3   = (const float*)d_in[10];
    const float* bn0g   = (const float*)d_in[11];
    const float* bn0b   = (const float*)d_in[12];
    const float* gatw   = (const float*)d_in[13];
    const float* attnl  = (const float*)d_in[14];
    const float* attnr  = (const float*)d_in[15];
    const float* gatb   = (const float*)d_in[16];
    const float* bn1g   = (const float*)d_in[17];
    const float* bn1b   = (const float*)d_in[18];
    const float* g2w1   = (const float*)d_in[19];
    const float* g2b1   = (const float*)d_in[20];
    const float* g2w2   = (const float*)d_in[21];
    const float* g2b2   = (const float*)d_in[22];
    const float* g2w3   = (const float*)d_in[23];
    const float* g2b3   = (const float*)d_in[24];
    const float* bn2g   = (const float*)d_in[25];
    const float* bn2b   = (const float*)d_in[26];
    float* out = (float*)d_out;

    static cudaStream_t s2 = 0;
    static cudaEvent_t evF = 0, evJ = 0;
    static int inited = 0;
    if (!inited) {
        cudaFuncSetAttribute(k_gemm_front, cudaFuncAttributeMaxDynamicSharedMemorySize, 73728);
        cudaFuncSetAttribute(k_gemm_tc,    cudaFuncAttributeMaxDynamicSharedMemorySize, 73728);
        cudaFuncSetAttribute(k_gemm_g2,    cudaFuncAttributeMaxDynamicSharedMemorySize, 73728);
        cudaStreamCreateWithFlags(&s2, cudaStreamNonBlocking);
        cudaEventCreateWithFlags(&evF, cudaEventDisableTiming);
        cudaEventCreateWithFlags(&evJ, cudaEventDisableTiming);
        inited = 1;
    }

    void *p_b0, *p_b1, *p_b2, *p_cnt, *p_el, *p_er;
    cudaGetSymbolAddress(&p_b0, d_bn0sum);
    cudaGetSymbolAddress(&p_b1, d_bn1sum);
    cudaGetSymbolAddress(&p_b2, d_bn2sum);
    cudaGetSymbolAddress(&p_cnt, d_counts);
    cudaGetSymbolAddress(&p_el, d_el);
    cudaGetSymbolAddress(&p_er, d_er);

    cudaMemsetAsync(p_b0, 0, 64*sizeof(float));
    cudaMemsetAsync(p_b1, 0, 2048*sizeof(float));
    cudaMemsetAsync(p_b2, 0, 64*sizeof(float));
    cudaMemsetAsync(p_el, 0, NN*HH*sizeof(float));
    cudaMemsetAsync(p_er, 0, NN*HH*sizeof(float));

    // side stream: gated2 B pack + CSR build
    cudaEventRecord(evF, 0);
    cudaStreamWaitEvent(s2, evF, 0);
    k_packB2<<<48, 256, 0, s2>>>(g2w1, g2w2, g2w3);
    cudaMemsetAsync(p_cnt, 0, NN*sizeof(int), s2);
    k_count<<<(EE + 255)/256, 256, 0, s2>>>(dst);
    k_scan<<<1, 1024, 0, s2>>>();
    k_fill<<<(EE + 255)/256, 256, 0, s2>>>(src, dst);
    cudaEventRecord(evJ, s2);

    // front: fp16 im2col + fp16 GEMM (writes apk) + bn0 finalize
    k_packB1<<<16, 256>>>(g1w1, g1w2, g1w3, rp_w);
    k_front_pack<<<MM2*32/256, 256>>>(X);
    k_gemm_front<<<MM2/128, 256, 73728>>>(g1b1, g1b2, g1b3, rp_b);
    k_bnfin0<<<1, 32>>>(bn0g, bn0b);

    // GAT projection GEMM (fp16, bn0 folded into W)
    k_packB<<<(HF*256 + 255)/256, 256>>>(gatw);
    k_bvec<<<128, 256>>>(gatw);
    k_gemm_tc<<<dim3(MPAD/128, HF/128), 256, 73728>>>(attnl, attnr);

    cudaStreamWaitEvent(0, evJ, 0);
    k_agg<<<(NN*32 + 255)/256, 256>>>(gatb);
    k_bn1stats<<<dim3(4, 40), 256>>>();
    k_bnfin1<<<4, 256>>>(bn1g, bn1b);

    // gated2: fp16 im2col + fp16 GEMM + gating epilogue
    k_g2_pack<<<MM2*128/256, 256>>>();
    k_gemm_g2<<<MM2/128, 256, 73728>>>(g2b1, g2b2, g2b3);

    k_out<<<(NN*CT + 2047)/2048, 256>>>(out, bn2g, bn2b);
}

// round 17
// speedup vs baseline: 1.4878x; 1.0287x over previous
#include <cuda_runtime.h>
#include <cuda_fp16.h>
#include <math.h>
#include <stdint.h>

#define NN 20000
#define CC 32
#define TT 8
#define HH 4
#define FF 256
#define HF 1024
#define EE 320000
#define CT 256
#define BEPS 1e-5f
#define SLOPE 0.2f

#define MPAD 20096
#define KPH 256
#define SAPITCH 72
#define MM2 160000
#define KA1H 96
#define FP1 104
#define KA2H 384

typedef unsigned long long ull;

// ---------------- scratch ----------------
__device__ float d_res[NN*CT];
__device__ float d_xn[NN*CT];
__device__ __half d_hh[(size_t)NN*HF];
__device__ float d_rst[NN*HF];
__device__ float d_el[NN*HH];
__device__ float d_er[NN*HH];
__device__ int   d_counts[NN];
__device__ int   d_rowstart[NN+1];
__device__ int   d_wptr[NN];
__device__ int   d_colsrc[EE];
__device__ float d_bn0sum[64];
__device__ float d_bn1sum[2048];
__device__ float d_bn2sum[64];
__device__ float d_ssc0[32];
__device__ float d_ssh0[32];
__device__ float d_bvec[1024];
__device__ float d_ssc[1024];
__device__ float d_ssh[1024];
__device__ __half d_apk[(size_t)MPAD*KPH];   // rows >= NN stay zero
__device__ __half d_bpk[(size_t)HF*KPH];
__device__ __half d_ai2h[(size_t)MM2*KA2H];
__device__ __half d_bp1[128*KA1H];
__device__ __half d_bp2h[96*KA2H];

// ---------------- helpers ----------------
__device__ __forceinline__ void cpasync16(uint32_t saddr, const void* g) {
    asm volatile("cp.async.cg.shared.global [%0], [%1], 16;" :: "r"(saddr), "l"(g));
}
__device__ __forceinline__ void h2f(unsigned u, float& a, float& b) {
    __half2 h = *(__half2*)&u;
    float2 f = __half22float2(h);
    a = f.x; b = f.y;
}
__device__ __forceinline__ void mma16816h(float* c, const unsigned* a, const unsigned* b) {
    asm volatile(
        "mma.sync.aligned.m16n8k16.row.col.f32.f16.f16.f32 "
        "{%0,%1,%2,%3}, {%4,%5,%6,%7}, {%8,%9}, {%0,%1,%2,%3};\n"
        : "+f"(c[0]), "+f"(c[1]), "+f"(c[2]), "+f"(c[3])
        : "r"(a[0]), "r"(a[1]), "r"(a[2]), "r"(a[3]), "r"(b[0]), "r"(b[1]));
}

// ---------------- front B pack (fp16) ----------------
__global__ void k_packB1(const float* __restrict__ w1, const float* __restrict__ w2,
                         const float* __restrict__ w3, const float* __restrict__ rp) {
    int i = blockIdx.x * 256 + threadIdx.x;
    if (i < 3072) {
        int co = i / 96, r = i % 96;
        d_bp1[(co)*KA1H + r]    = __float2half(w1[i]);
        d_bp1[(32+co)*KA1H + r] = __float2half(w2[i]);
        d_bp1[(64+co)*KA1H + r] = __float2half(w3[i]);
    } else if (i < 4096) {
        int j = i - 3072, co = j >> 5, ci = j & 31;
        d_bp1[(96+co)*KA1H + ci*3 + 1] = __float2half(rp[j]);
    }
}

// ---------------- front GEMM (fp16, K=96, fused im2col) + gating epilogue ----
__global__ __launch_bounds__(256) void k_gemm_front(
    const float* __restrict__ X,
    const float* __restrict__ b1, const float* __restrict__ b2,
    const float* __restrict__ b3, const float* __restrict__ rpb)
{
    extern __shared__ __align__(16) char gsm[];
    __half* As = (__half*)gsm;                      // 128*104 halves
    __half* Bs = As + 128*FP1;                      // 128*104 halves
    float*  Xf = (float*)(gsm + 2*128*FP1*2);       // 16*256 floats (16KB)
    int tid = threadIdx.x;
    int m0 = blockIdx.x * 128;
    int node0 = m0 >> 3;
    int w = tid >> 5, lane = tid & 31;
    int wm = (w >> 2) * 64, wn = (w & 3) * 32;
    int g = lane >> 2, t = lane & 3;
    uint32_t sB = (uint32_t)__cvta_generic_to_shared(Bs);
    uint32_t sX = (uint32_t)__cvta_generic_to_shared(Xf);

    float acc[4][4][4];
    #pragma unroll
    for (int i = 0; i < 4; i++)
        #pragma unroll
        for (int j = 0; j < 4; j++)
            #pragma unroll
            for (int q = 0; q < 4; q++) acc[i][j][q] = 0.f;

    // load B tile (128x96 halves) + X tile (16 nodes x 256 floats)
    #pragma unroll
    for (int p = 0; p < 6; p++) {
        int l = tid + p*256;
        int row = l / 12, c = (l % 12) * 8;
        cpasync16(sB + (row*FP1 + c)*2, &d_bp1[row*KA1H + c]);
    }
    #pragma unroll
    for (int p = 0; p < 4; p++) {
        int l = tid + p*256;
        cpasync16(sX + l*16, &X[(size_t)node0*256 + l*4]);
    }
    asm volatile("cp.async.commit_group;");
    asm volatile("cp.async.wait_group 0;");
    __syncthreads();

    // in-kernel im2col: build As (128 x 96 halves)
    #pragma unroll
    for (int p = 0; p < 6; p++) {
        int l = tid + p*256;
        int row = l / 12, cq = l % 12;
        int nl = row >> 3, tt0 = row & 7;
        const float* xr = &Xf[nl*256];
        __half hb[8];
        #pragma unroll
        for (int jj = 0; jj < 8; jj++) {
            int j = cq*8 + jj;
            int ci = j / 3, k = j % 3, tt = tt0 + k - 1;
            float v = (tt >= 0 && tt < 8) ? xr[ci*8 + tt] : 0.f;
            hb[jj] = __float2half(v);
        }
        *(uint4*)&As[row*FP1 + cq*8] = *(uint4*)hb;
    }
    __syncthreads();

    #pragma unroll
    for (int kk = 0; kk < 6; kk++) {
        int kbx = kk * 16;
        unsigned afr[4][4];
        #pragma unroll
        for (int mi = 0; mi < 4; mi++) {
            int r0 = wm + mi*16 + g;
            afr[mi][0] = *(const unsigned*)&As[r0    *FP1 + kbx + 2*t];
            afr[mi][1] = *(const unsigned*)&As[(r0+8)*FP1 + kbx + 2*t];
            afr[mi][2] = *(const unsigned*)&As[r0    *FP1 + kbx + 2*t + 8];
            afr[mi][3] = *(const unsigned*)&As[(r0+8)*FP1 + kbx + 2*t + 8];
        }
        unsigned bfr[4][2];
        #pragma unroll
        for (int nj = 0; nj < 4; nj++) {
            int br = wn + nj*8 + g;
            bfr[nj][0] = *(const unsigned*)&Bs[br*FP1 + kbx + 2*t];
            bfr[nj][1] = *(const unsigned*)&Bs[br*FP1 + kbx + 2*t + 8];
        }
        #pragma unroll
        for (int mi = 0; mi < 4; mi++)
            #pragma unroll
            for (int nj = 0; nj < 4; nj++)
                mma16816h(acc[mi][nj], afr[mi], bfr[nj]);
    }
    __syncthreads();

    float* sm = (float*)gsm;
    float* sstats = sm + 128*132;
    #pragma unroll
    for (int mi = 0; mi < 4; mi++) {
        int r0 = wm + mi*16 + g;
        #pragma unroll
        for (int nj = 0; nj < 4; nj++) {
            int col = wn + nj*8 + 2*t;
            *(float2*)&sm[r0*132 + col]     = make_float2(acc[mi][nj][0], acc[mi][nj][1]);
            *(float2*)&sm[(r0+8)*132 + col] = make_float2(acc[mi][nj][2], acc[mi][nj][3]);
        }
    }
    if (tid < 64) sstats[tid] = 0.f;
    __syncthreads();

    float B1 = b1[lane], B2 = b2[lane], B3 = b3[lane], BR = rpb[lane];
    float s = 0.f, q = 0.f;
    #pragma unroll
    for (int rep = 0; rep < 2; rep++) {
        int nl = rep*8 + w;
        int n = node0 + nl;
        __half hbuf[8];
        float r8[8];
        #pragma unroll
        for (int tt = 0; tt < 8; tt++) {
            const float* rw = &sm[(nl*8 + tt)*132];
            float a1 = rw[lane] + B1, a2 = rw[lane+32] + B2;
            float a3 = rw[lane+64] + B3, rr = rw[lane+96] + BR;
            float gg = a1*(1.f/(1.f+expf(-a2))) + a3;
            gg = fmaxf(gg, 0.f);
            hbuf[tt] = __float2half(gg);
            r8[tt] = rr;
            s += gg; q += gg*gg;
        }
        *(uint4*)&d_apk[(size_t)n*KPH + lane*8] = *(uint4*)hbuf;
        *(float4*)&d_res[n*256 + lane*8]     = make_float4(r8[0],r8[1],r8[2],r8[3]);
        *(float4*)&d_res[n*256 + lane*8 + 4] = make_float4(r8[4],r8[5],r8[6],r8[7]);
    }
    atomicAdd(&sstats[lane], s);
    atomicAdd(&sstats[32+lane], q);
    __syncthreads();
    if (tid < 32) {
        atomicAdd(&d_bn0sum[tid],    sstats[tid]);
        atomicAdd(&d_bn0sum[32+tid], sstats[32+tid]);
    }
}

// ---------------- bn0 finalize ----------------
__global__ void k_bnfin0(const float* __restrict__ bn0g, const float* __restrict__ bn0b) {
    int t = threadIdx.x;
    if (t < 32) {
        float inv = 1.f/(float)(NN*TT);
        float mean = d_bn0sum[t]*inv;
        float var  = d_bn0sum[32+t]*inv - mean*mean;
        float a = bn0g[t]*rsqrtf(var + BEPS);
        d_ssc0[t] = a; d_ssh0[t] = bn0b[t] - mean*a;
    }
}

// ---------------- GAT W prep: scaled fp16 pack + bvec (merged) ----------------
__global__ __launch_bounds__(256) void k_prepW(const float* __restrict__ W) {
    __shared__ float red[256];
    int o = blockIdx.x;
    int k = threadIdx.x;
    float wv = W[o*256 + k];
    d_bpk[(size_t)o*KPH + k] = __float2half(wv * d_ssc0[k >> 3]);
    red[k] = d_ssh0[k >> 3] * wv;
    __syncthreads();
    #pragma unroll
    for (int off = 128; off; off >>= 1) {
        if (k < off) red[k] += red[k + off];
        __syncthreads();
    }
    if (k == 0) d_bvec[o] = red[0];
}

// ---------------- GAT GEMM (fp16, K=256) + bvec + el/er, fp16 h out ----------
__global__ __launch_bounds__(256) void k_gemm_tc(const float* __restrict__ attn_l,
                                                 const float* __restrict__ attn_r) {
    extern __shared__ __align__(16) char gsm[];
    __half* As = (__half*)gsm;
    __half* Bs = As + 2*128*SAPITCH;

    int tid = threadIdx.x;
    int m0 = blockIdx.x * 128, n0 = blockIdx.y * 128;
    int w = tid >> 5, lane = tid & 31;
    int wm = (w >> 2) * 64, wn = (w & 3) * 32;
    int g = lane >> 2, t = lane & 3;

    uint32_t sA = (uint32_t)__cvta_generic_to_shared(As);
    uint32_t sB = (uint32_t)__cvta_generic_to_shared(Bs);

    float acc[4][4][4];
    #pragma unroll
    for (int i = 0; i < 4; i++)
        #pragma unroll
        for (int j = 0; j < 4; j++)
            #pragma unroll
            for (int q = 0; q < 4; q++) acc[i][j][q] = 0.f;

    int row4 = tid >> 3, ci4 = tid & 7;

    #pragma unroll
    for (int r = 0; r < 4; r++) {
        int row = row4 + r*32;
        cpasync16(sA + (row*SAPITCH + ci4*8)*2, &d_apk[(size_t)(m0 + row)*KPH + ci4*8]);
        cpasync16(sB + (row*SAPITCH + ci4*8)*2, &d_bpk[(size_t)(n0 + row)*KPH + ci4*8]);
    }
    asm volatile("cp.async.commit_group;");

    for (int it = 0; it < 4; it++) {
        if (it < 3) {
            int k0 = (it + 1) * 64;
            int buf = (it + 1) & 1;
            #pragma unroll
            for (int r = 0; r < 4; r++) {
                int row = row4 + r*32;
                cpasync16(sA + (buf*128*SAPITCH + row*SAPITCH + ci4*8)*2,
                          &d_apk[(size_t)(m0 + row)*KPH + k0 + ci4*8]);
                cpasync16(sB + (buf*128*SAPITCH + row*SAPITCH + ci4*8)*2,
                          &d_bpk[(size_t)(n0 + row)*KPH + k0 + ci4*8]);
            }
            asm volatile("cp.async.commit_group;");
            asm volatile("cp.async.wait_group 1;");
        } else {
            asm volatile("cp.async.wait_group 0;");
        }
        __syncthreads();

        const __half* Ab = As + (it & 1)*128*SAPITCH;
        const __half* Bb = Bs + (it & 1)*128*SAPITCH;
        #pragma unroll
        for (int kk = 0; kk < 4; kk++) {
            int kbx = kk * 16;
            unsigned afr[4][4];
            #pragma unroll
            for (int mi = 0; mi < 4; mi++) {
                int r0 = wm + mi*16 + g;
                afr[mi][0] = *(const unsigned*)&Ab[r0      *SAPITCH + kbx + 2*t];
                afr[mi][1] = *(const unsigned*)&Ab[(r0 + 8)*SAPITCH + kbx + 2*t];
                afr[mi][2] = *(const unsigned*)&Ab[r0      *SAPITCH + kbx + 2*t + 8];
                afr[mi][3] = *(const unsigned*)&Ab[(r0 + 8)*SAPITCH + kbx + 2*t + 8];
            }
            unsigned bfr[4][2];
            #pragma unroll
            for (int nj = 0; nj < 4; nj++) {
                int br = wn + nj*8 + g;
                bfr[nj][0] = *(const unsigned*)&Bb[br*SAPITCH + kbx + 2*t];
                bfr[nj][1] = *(const unsigned*)&Bb[br*SAPITCH + kbx + 2*t + 8];
            }
            #pragma unroll
            for (int mi = 0; mi < 4; mi++)
                #pragma unroll
                for (int nj = 0; nj < 4; nj++)
                    mma16816h(acc[mi][nj], afr[mi], bfr[nj]);
        }
        __syncthreads();
    }

    #pragma unroll
    for (int nj = 0; nj < 4; nj++) {
        int col = n0 + wn + nj*8 + 2*t;
        float bv0 = __ldg(&d_bvec[col]), bv1 = __ldg(&d_bvec[col+1]);
        #pragma unroll
        for (int mi = 0; mi < 4; mi++) {
            acc[mi][nj][0] += bv0; acc[mi][nj][1] += bv1;
            acc[mi][nj][2] += bv0; acc[mi][nj][3] += bv1;
        }
    }

    float pel[4][2], per_[4][2];
    #pragma unroll
    for (int mi = 0; mi < 4; mi++) { pel[mi][0]=pel[mi][1]=per_[mi][0]=per_[mi][1]=0.f; }
    #pragma unroll
    for (int mi = 0; mi < 4; mi++)
        #pragma unroll
        for (int nj = 0; nj < 4; nj++) {
            int col = n0 + wn + nj*8 + 2*t;
            float al0 = __ldg(&attn_l[col]), al1 = __ldg(&attn_l[col+1]);
            float ar0 = __ldg(&attn_r[col]), ar1 = __ldg(&attn_r[col+1]);
            pel[mi][0]  += acc[mi][nj][0]*al0 + acc[mi][nj][1]*al1;
            pel[mi][1]  += acc[mi][nj][2]*al0 + acc[mi][nj][3]*al1;
            per_[mi][0] += acc[mi][nj][0]*ar0 + acc[mi][nj][1]*ar1;
            per_[mi][1] += acc[mi][nj][2]*ar0 + acc[mi][nj][3]*ar1;
        }
    #pragma unroll
    for (int mi = 0; mi < 4; mi++)
        #pragma unroll
        for (int h2 = 0; h2 < 2; h2++) {
            pel[mi][h2]  += __shfl_xor_sync(0xffffffffu, pel[mi][h2], 1);
            pel[mi][h2]  += __shfl_xor_sync(0xffffffffu, pel[mi][h2], 2);
            per_[mi][h2] += __shfl_xor_sync(0xffffffffu, per_[mi][h2], 1);
            per_[mi][h2] += __shfl_xor_sync(0xffffffffu, per_[mi][h2], 2);
        }
    int head = n0 >> 8;
    if (t == 0) {
        #pragma unroll
        for (int mi = 0; mi < 4; mi++) {
            int r0 = m0 + wm + mi*16 + g;
            if (r0 < NN)     { atomicAdd(&d_el[r0*4 + head], pel[mi][0]);
                               atomicAdd(&d_er[r0*4 + head], per_[mi][0]); }
            if (r0 + 8 < NN) { atomicAdd(&d_el[(r0+8)*4 + head], pel[mi][1]);
                               atomicAdd(&d_er[(r0+8)*4 + head], per_[mi][1]); }
        }
    }

    #pragma unroll
    for (int mi = 0; mi < 4; mi++) {
        int r0 = m0 + wm + mi*16 + g;
        #pragma unroll
        for (int nj = 0; nj < 4; nj++) {
            int col = n0 + wn + nj*8 + 2*t;
            if (r0 < NN)
                *(__half2*)&d_hh[(size_t)r0*HF + col] =
                    __float22half2_rn(make_float2(acc[mi][nj][0], acc[mi][nj][1]));
            if (r0 + 8 < NN)
                *(__half2*)&d_hh[(size_t)(r0+8)*HF + col] =
                    __float22half2_rn(make_float2(acc[mi][nj][2], acc[mi][nj][3]));
        }
    }
}

// ---------------- CSR build ----------------
__global__ void k_count(const int* __restrict__ dst) {
    int e = blockIdx.x * blockDim.x + threadIdx.x;
    if (e < EE) atomicAdd(&d_counts[dst[e]], 1);
}

__global__ __launch_bounds__(1024) void k_scan() {
    __shared__ int part[1024];
    int tid = threadIdx.x;
    int beg = tid * 20, end = min(beg + 20, NN);
    int s = 0;
    for (int i = beg; i < end; i++) s += d_counts[i];
    part[tid] = s;
    __syncthreads();
    for (int off = 1; off < 1024; off <<= 1) {
        int v = 0;
        if (tid >= off) v = part[tid - off];
        __syncthreads();
        if (tid >= off) part[tid] += v;
        __syncthreads();
    }
    int run = (tid == 0) ? 0 : part[tid - 1];
    for (int i = beg; i < end; i++) {
        d_rowstart[i] = run; d_wptr[i] = run;
        run += d_counts[i];
    }
    if (tid == 1023) d_rowstart[NN] = run;
}

__global__ void k_fill(const int* __restrict__ src, const int* __restrict__ dst) {
    int e = blockIdx.x * blockDim.x + threadIdx.x;
    if (e < EE) {
        int p = atomicAdd(&d_wptr[dst[e]], 1);
        d_colsrc[p] = src[e];
    }
}

// ---------------- GAT aggregation (fp16 gather) ----------------
__device__ __forceinline__ float lrelu(float x) { return x > 0.f ? x : SLOPE * x; }

__global__ __launch_bounds__(256) void k_agg(const float* __restrict__ bias) {
    int n = (blockIdx.x * blockDim.x + threadIdx.x) >> 5;
    int lane = threadIdx.x & 31;
    if (n >= NN) return;
    int beg = d_rowstart[n], end = d_rowstart[n+1];
    float er0 = d_er[n*4+0], er1 = d_er[n*4+1], er2 = d_er[n*4+2], er3 = d_er[n*4+3];

    float e0[4], e1[4], e2[4], e3[4];
    #pragma unroll
    for (int s = 0; s < 4; s++) {
        int j = beg + s*32 + lane;
        if (j < end) {
            int sc = d_colsrc[j];
            e0[s] = lrelu(d_el[sc*4+0] + er0);
            e1[s] = lrelu(d_el[sc*4+1] + er1);
            e2[s] = lrelu(d_el[sc*4+2] + er2);
            e3[s] = lrelu(d_el[sc*4+3] + er3);
        } else { e0[s] = e1[s] = e2[s] = e3[s] = -1e30f; }
    }
    float m0 = -1e30f, m1 = -1e30f, m2 = -1e30f, m3 = -1e30f;
    #pragma unroll
    for (int s = 0; s < 4; s++) {
        m0 = fmaxf(m0, e0[s]); m1 = fmaxf(m1, e1[s]);
        m2 = fmaxf(m2, e2[s]); m3 = fmaxf(m3, e3[s]);
    }
    #pragma unroll
    for (int off = 16; off; off >>= 1) {
        m0 = fmaxf(m0, __shfl_xor_sync(0xffffffffu, m0, off));
        m1 = fmaxf(m1, __shfl_xor_sync(0xffffffffu, m1, off));
        m2 = fmaxf(m2, __shfl_xor_sync(0xffffffffu, m2, off));
        m3 = fmaxf(m3, __shfl_xor_sync(0xffffffffu, m3, off));
    }
    float s0 = 0.f, s1 = 0.f, s2 = 0.f, s3 = 0.f;
    #pragma unroll
    for (int s = 0; s < 4; s++) {
        e0[s] = expf(e0[s] - m0); s0 += e0[s];
        e1[s] = expf(e1[s] - m1); s1 += e1[s];
        e2[s] = expf(e2[s] - m2); s2 += e2[s];
        e3[s] = expf(e3[s] - m3); s3 += e3[s];
    }
    #pragma unroll
    for (int off = 16; off; off >>= 1) {
        s0 += __shfl_xor_sync(0xffffffffu, s0, off);
        s1 += __shfl_xor_sync(0xffffffffu, s1, off);
        s2 += __shfl_xor_sync(0xffffffffu, s2, off);
        s3 += __shfl_xor_sync(0xffffffffu, s3, off);
    }
    float i0 = s0 > 0.f ? 1.f/s0 : 0.f;
    float i1 = s1 > 0.f ? 1.f/s1 : 0.f;
    float i2 = s2 > 0.f ? 1.f/s2 : 0.f;
    float i3 = s3 > 0.f ? 1.f/s3 : 0.f;
    #pragma unroll
    for (int s = 0; s < 4; s++) { e0[s] *= i0; e1[s] *= i1; e2[s] *= i2; e3[s] *= i3; }

    float acc[4][8];
    #pragma unroll
    for (int j = 0; j < 4; j++)
        #pragma unroll
        for (int e = 0; e < 8; e++) acc[j][e] = 0.f;

    #pragma unroll
    for (int s = 0; s < 4; s++) {
        int base = beg + s*32;
        int lim = end - base;
        if (lim <= 0) break;
        if (lim > 32) lim = 32;
        for (int u = 0; u < lim; u++) {
            int sc = d_colsrc[base + u];
            float wj[4];
            wj[0] = __shfl_sync(0xffffffffu, e0[s], u);
            wj[1] = __shfl_sync(0xffffffffu, e1[s], u);
            wj[2] = __shfl_sync(0xffffffffu, e2[s], u);
            wj[3] = __shfl_sync(0xffffffffu, e3[s], u);
            const uint4* hp = (const uint4*)&d_hh[(size_t)sc*HF];
            #pragma unroll
            for (int j = 0; j < 4; j++) {
                uint4 v = hp[j*32 + lane];
                float w = wj[j];
                float a, b;
                h2f(v.x, a, b); acc[j][0] += w*a; acc[j][1] += w*b;
                h2f(v.y, a, b); acc[j][2] += w*a; acc[j][3] += w*b;
                h2f(v.z, a, b); acc[j][4] += w*a; acc[j][5] += w*b;
                h2f(v.w, a, b); acc[j][6] += w*a; acc[j][7] += w*b;
            }
        }
    }
    #pragma unroll
    for (int j = 0; j < 4; j++) {
        int f0 = j*256 + lane*8;
        float4 b0 = __ldg((const float4*)&bias[f0]);
        float4 b1 = __ldg((const float4*)&bias[f0+4]);
        float4 v0 = make_float4(fmaxf(acc[j][0]+b0.x,0.f), fmaxf(acc[j][1]+b0.y,0.f),
                                fmaxf(acc[j][2]+b0.z,0.f), fmaxf(acc[j][3]+b0.w,0.f));
        float4 v1 = make_float4(fmaxf(acc[j][4]+b1.x,0.f), fmaxf(acc[j][5]+b1.y,0.f),
                                fmaxf(acc[j][6]+b1.z,0.f), fmaxf(acc[j][7]+b1.w,0.f));
        *(float4*)&d_rst[(size_t)n*HF + f0]     = v0;
        *(float4*)&d_rst[(size_t)n*HF + f0 + 4] = v1;
    }
}

// ---------------- bn1 stats ----------------
__global__ __launch_bounds__(256) void k_bn1stats() {
    int f = blockIdx.x * 256 + threadIdx.x;
    int n0 = blockIdx.y * 250;
    float s = 0.f, q = 0.f;
    for (int n = n0; n < n0 + 250; n++) {
        float v = d_rst[(size_t)n*HF + f];
        s += v; q += v*v;
    }
    atomicAdd(&d_bn1sum[f], s);
    atomicAdd(&d_bn1sum[1024 + f], q);
}

__global__ void k_bnfin1(const float* __restrict__ bn1g, const float* __restrict__ bn1b) {
    int f = blockIdx.x * 256 + threadIdx.x;
    if (f < 1024) {
        float invN = 1.f/(float)NN;
        float mean = d_bn1sum[f]*invN;
        float var  = d_bn1sum[1024+f]*invN - mean*mean;
        float a = bn1g[f]*rsqrtf(var + BEPS);
        d_ssc[f] = a; d_ssh[f] = bn1b[f] - mean*a;
    }
}

// ---------------- gated2 im2col pack (fp16, bn1 apply fused) ----------------
__global__ __launch_bounds__(256) void k_g2_pack() {
    int idx = blockIdx.x * 256 + threadIdx.x;
    int m = idx >> 7, ci = idx & 127;
    int n = m >> 3, t = m & 7;
    int f = ci*8 + t;
    const float* rr = &d_rst[(size_t)n*HF];
    float x0 = rr[f]*__ldg(&d_ssc[f]) + __ldg(&d_ssh[f]);
    float xm = (t > 0) ? rr[f-1]*__ldg(&d_ssc[f-1]) + __ldg(&d_ssh[f-1]) : 0.f;
    float xp = (t < 7) ? rr[f+1]*__ldg(&d_ssc[f+1]) + __ldg(&d_ssh[f+1]) : 0.f;
    size_t ab = (size_t)m*KA2H + ci*3;
    d_ai2h[ab+0] = __float2half(xm);
    d_ai2h[ab+1] = __float2half(x0);
    d_ai2h[ab+2] = __float2half(xp);
}

// ---------------- gated2 B pack (fp16) ----------------
__global__ void k_packB2(const float* __restrict__ w1, const float* __restrict__ w2,
                         const float* __restrict__ w3) {
    int i = blockIdx.x * 256 + threadIdx.x;
    if (i < 12288) {
        int co = i / 384, r = i % 384;
        d_bp2h[(co)*KA2H + r]    = __float2half(w1[i]);
        d_bp2h[(32+co)*KA2H + r] = __float2half(w2[i]);
        d_bp2h[(64+co)*KA2H + r] = __float2half(w3[i]);
    }
}

// ---------------- gated2 GEMM (fp16, N=96, K=384) + gating epilogue ----------
__global__ __launch_bounds__(256) void k_gemm_g2(
    const float* __restrict__ b1, const float* __restrict__ b2,
    const float* __restrict__ b3)
{
    extern __shared__ __align__(16) char gsm[];
    __half* As = (__half*)gsm;
    __half* Bs = As + 2*128*SAPITCH;
    int tid = threadIdx.x;
    int m0 = blockIdx.x * 128;
    int w = tid >> 5, lane = tid & 31;
    int wm = (w >> 2) * 64, wn = (w & 3) * 24;
    int g = lane >> 2, t = lane & 3;
    uint32_t sA = (uint32_t)__cvta_generic_to_shared(As);
    uint32_t sB = (uint32_t)__cvta_generic_to_shared(Bs);

    float acc[4][3][4];
    #pragma unroll
    for (int i = 0; i < 4; i++)
        #pragma unroll
        for (int j = 0; j < 3; j++)
            #pragma unroll
            for (int q = 0; q < 4; q++) acc[i][j][q] = 0.f;

    int row4 = tid >> 3, ci4 = tid & 7;

    #pragma unroll
    for (int r = 0; r < 4; r++) {
        int row = row4 + r*32;
        cpasync16(sA + (row*SAPITCH + ci4*8)*2, &d_ai2h[(size_t)(m0 + row)*KA2H + ci4*8]);
        if (r < 3)
            cpasync16(sB + (row*SAPITCH + ci4*8)*2, &d_bp2h[row*KA2H + ci4*8]);
    }
    asm volatile("cp.async.commit_group;");

    for (int it = 0; it < 6; it++) {
        if (it < 5) {
            int k0 = (it + 1) * 64;
            int buf = (it + 1) & 1;
            #pragma unroll
            for (int r = 0; r < 4; r++) {
                int row = row4 + r*32;
                cpasync16(sA + (buf*128*SAPITCH + row*SAPITCH + ci4*8)*2,
                          &d_ai2h[(size_t)(m0 + row)*KA2H + k0 + ci4*8]);
                if (r < 3)
                    cpasync16(sB + (buf*96*SAPITCH + row*SAPITCH + ci4*8)*2,
                              &d_bp2h[row*KA2H + k0 + ci4*8]);
            }
            asm volatile("cp.async.commit_group;");
            asm volatile("cp.async.wait_group 1;");
        } else {
            asm volatile("cp.async.wait_group 0;");
        }
        __syncthreads();
        const __half* Ab = As + (it & 1)*128*SAPITCH;
        const __half* Bb = Bs + (it & 1)*96*SAPITCH;
        #pragma unroll
        for (int kk = 0; kk < 4; kk++) {
            int kbx = kk * 16;
            unsigned afr[4][4];
            #pragma unroll
            for (int mi = 0; mi < 4; mi++) {
                int r0 = wm + mi*16 + g;
                afr[mi][0] = *(const unsigned*)&Ab[r0      *SAPITCH + kbx + 2*t];
                afr[mi][1] = *(const unsigned*)&Ab[(r0 + 8)*SAPITCH + kbx + 2*t];
                afr[mi][2] = *(const unsigned*)&Ab[r0      *SAPITCH + kbx + 2*t + 8];
                afr[mi][3] = *(const unsigned*)&Ab[(r0 + 8)*SAPITCH + kbx + 2*t + 8];
            }
            unsigned bfr[3][2];
            #pragma unroll
            for (int nj = 0; nj < 3; nj++) {
                int br = wn + nj*8 + g;
                bfr[nj][0] = *(const unsigned*)&Bb[br*SAPITCH + kbx + 2*t];
                bfr[nj][1] = *(const unsigned*)&Bb[br*SAPITCH + kbx + 2*t + 8];
            }
            #pragma unroll
            for (int mi = 0; mi < 4; mi++)
                #pragma unroll
                for (int nj = 0; nj < 3; nj++)
                    mma16816h(acc[mi][nj], afr[mi], bfr[nj]);
        }
        __syncthreads();
    }

    float* sm = (float*)gsm;
    float* sstats = sm + 128*132;
    #pragma unroll
    for (int mi = 0; mi < 4; mi++) {
        int r0 = wm + mi*16 + g;
        #pragma unroll
        for (int nj = 0; nj < 3; nj++) {
            int col = wn + nj*8 + 2*t;
            *(float2*)&sm[r0*132 + col]     = make_float2(acc[mi][nj][0], acc[mi][nj][1]);
            *(float2*)&sm[(r0+8)*132 + col] = make_float2(acc[mi][nj][2], acc[mi][nj][3]);
        }
    }
    if (tid < 64) sstats[tid] = 0.f;
    __syncthreads();

    int nb = m0 >> 3;
    float B1 = b1[lane], B2 = b2[lane], B3 = b3[lane];
    float s = 0.f, q = 0.f;
    #pragma unroll
    for (int rep = 0; rep < 2; rep++) {
        int nl = rep*8 + w;
        int n = nb + nl;
        float g8[8];
        #pragma unroll
        for (int tt = 0; tt < 8; tt++) {
            const float* rw = &sm[(nl*8 + tt)*132];
            float a1 = rw[lane] + B1, a2 = rw[lane+32] + B2, a3 = rw[lane+64] + B3;
            float gg = a1*(1.f/(1.f+expf(-a2))) + a3;
            gg = fmaxf(gg, 0.f);
            g8[tt] = gg;
            s += gg; q += gg*gg;
        }
        *(float4*)&d_xn[n*256 + lane*8]     = make_float4(g8[0],g8[1],g8[2],g8[3]);
        *(float4*)&d_xn[n*256 + lane*8 + 4] = make_float4(g8[4],g8[5],g8[6],g8[7]);
    }
    atomicAdd(&sstats[lane], s);
    atomicAdd(&sstats[32+lane], q);
    __syncthreads();
    if (tid < 32) {
        atomicAdd(&d_bn2sum[tid],    sstats[tid]);
        atomicAdd(&d_bn2sum[32+tid], sstats[32+tid]);
    }
}

// ---------------- final ----------------
__global__ void k_out(float* __restrict__ out, const float* __restrict__ bn2g,
                      const float* __restrict__ bn2b) {
    __shared__ float ssc[32], ssh[32];
    int tid = threadIdx.x;
    if (tid < 32) {
        float inv = 1.f/(float)(NN*TT);
        float mean = d_bn2sum[tid]*inv;
        float var  = d_bn2sum[32+tid]*inv - mean*mean;
        float a = bn2g[tid]*rsqrtf(var + BEPS);
        ssc[tid] = a; ssh[tid] = bn2b[tid] - mean*a;
    }
    __syncthreads();
    int base = blockIdx.x * 2048;
    for (int o = tid; o < 2048; o += 256) {
        int i = base + o;
        if (i < NN*CT) {
            int c = (i >> 3) & 31;
            float v = d_xn[i]*ssc[c] + ssh[c] + d_res[i];
            out[i] = v > 0.f ? v : 0.f;
        }
    }
}

// ---------------- launch ----------------
extern "C" void kernel_launch(void* const* d_in, const int* in_sizes, int n_in,
                              void* d_out, int out_size) {
    const float* X      = (const float*)d_in[0];
    const int*   src    = (const int*)  d_in[1];
    const int*   dst    = (const int*)  d_in[2];
    const float* rp_w   = (const float*)d_in[3];
    const float* rp_b   = (const float*)d_in[4];
    const float* g1w1   = (const float*)d_in[5];
    const float* g1b1   = (const float*)d_in[6];
    const float* g1w2   = (const float*)d_in[7];
    const float* g1b2   = (const float*)d_in[8];
    const float* g1w3   = (const float*)d_in[9];
    const float* g1b3   = (const float*)d_in[10];
    const float* bn0g   = (const float*)d_in[11];
    const float* bn0b   = (const float*)d_in[12];
    const float* gatw   = (const float*)d_in[13];
    const float* attnl  = (const float*)d_in[14];
    const float* attnr  = (const float*)d_in[15];
    const float* gatb   = (const float*)d_in[16];
    const float* bn1g   = (const float*)d_in[17];
    const float* bn1b   = (const float*)d_in[18];
    const float* g2w1   = (const float*)d_in[19];
    const float* g2b1   = (const float*)d_in[20];
    const float* g2w2   = (const float*)d_in[21];
    const float* g2b2   = (const float*)d_in[22];
    const float* g2w3   = (const float*)d_in[23];
    const float* g2b3   = (const float*)d_in[24];
    const float* bn2g   = (const float*)d_in[25];
    const float* bn2b   = (const float*)d_in[26];
    float* out = (float*)d_out;

    static cudaStream_t s2 = 0;
    static cudaEvent_t evF = 0, evJ = 0;
    static int inited = 0;
    if (!inited) {
        cudaFuncSetAttribute(k_gemm_front, cudaFuncAttributeMaxDynamicSharedMemorySize, 73728);
        cudaFuncSetAttribute(k_gemm_tc,    cudaFuncAttributeMaxDynamicSharedMemorySize, 73728);
        cudaFuncSetAttribute(k_gemm_g2,    cudaFuncAttributeMaxDynamicSharedMemorySize, 73728);
        cudaStreamCreateWithFlags(&s2, cudaStreamNonBlocking);
        cudaEventCreateWithFlags(&evF, cudaEventDisableTiming);
        cudaEventCreateWithFlags(&evJ, cudaEventDisableTiming);
        inited = 1;
    }

    void *p_b0, *p_b1, *p_b2, *p_cnt, *p_el, *p_er;
    cudaGetSymbolAddress(&p_b0, d_bn0sum);
    cudaGetSymbolAddress(&p_b1, d_bn1sum);
    cudaGetSymbolAddress(&p_b2, d_bn2sum);
    cudaGetSymbolAddress(&p_cnt, d_counts);
    cudaGetSymbolAddress(&p_el, d_el);
    cudaGetSymbolAddress(&p_er, d_er);

    cudaMemsetAsync(p_b0, 0, 64*sizeof(float));
    cudaMemsetAsync(p_b1, 0, 2048*sizeof(float));
    cudaMemsetAsync(p_b2, 0, 64*sizeof(float));
    cudaMemsetAsync(p_el, 0, NN*HH*sizeof(float));
    cudaMemsetAsync(p_er, 0, NN*HH*sizeof(float));

    // side stream: gated2 B pack + CSR build
    cudaEventRecord(evF, 0);
    cudaStreamWaitEvent(s2, evF, 0);
    k_packB2<<<48, 256, 0, s2>>>(g2w1, g2w2, g2w3);
    cudaMemsetAsync(p_cnt, 0, NN*sizeof(int), s2);
    k_count<<<(EE + 255)/256, 256, 0, s2>>>(dst);
    k_scan<<<1, 1024, 0, s2>>>();
    k_fill<<<(EE + 255)/256, 256, 0, s2>>>(src, dst);
    cudaEventRecord(evJ, s2);

    // front: fused im2col + fp16 GEMM (writes apk) + bn0 finalize
    k_packB1<<<16, 256>>>(g1w1, g1w2, g1w3, rp_w);
    k_gemm_front<<<MM2/128, 256, 73728>>>(X, g1b1, g1b2, g1b3, rp_b);
    k_bnfin0<<<1, 32>>>(bn0g, bn0b);

    // GAT projection GEMM (fp16, bn0 folded into W; packB+bvec merged)
    k_prepW<<<1024, 256>>>(gatw);
    k_gemm_tc<<<dim3(MPAD/128, HF/128), 256, 73728>>>(attnl, attnr);

    cudaStreamWaitEvent(0, evJ, 0);
    k_agg<<<(NN*32 + 255)/256, 256>>>(gatb);
    k_bn1stats<<<dim3(4, 80), 256>>>();
    k_bnfin1<<<4, 256>>>(bn1g, bn1b);

    // gated2: fp16 im2col + fp16 GEMM + gating epilogue
    k_g2_pack<<<MM2*128/256, 256>>>();
    k_gemm_g2<<<MM2/128, 256, 73728>>>(g2b1, g2b2, g2b3);

    k_out<<<(NN*CT + 2047)/2048, 256>>>(out, bn2g, bn2b);
}